// round 4
// baseline (speedup 1.0000x reference)
#include <cuda_runtime.h>
#include <math.h>

#define N_NODES 100000
#define N_EDGES 1600000
#define SCAN_NB ((N_NODES + 1023) / 1024)   // 98 blocks

// ---------------- scratch (device globals: no allocation allowed) ----------
__device__ __align__(16) float g_h[N_NODES * 64];    // h = act(X) @ W (raw)
__device__ __align__(16) float g_agg[N_NODES * 64];  // aggregation buffer
__device__ float g_dis[N_NODES];          // rsqrt(deg+1)
__device__ int   g_cnt[N_NODES];          // in-degree (by dst)
__device__ int   g_rowstart[N_NODES];     // CSR row offsets (exclusive scan)
__device__ int   g_fill[N_NODES];         // atomic fill cursors
__device__ int   g_blocksum[SCAN_NB];
__device__ int   g_src[N_EDGES];          // decoded edge endpoints (int32)
__device__ int   g_dst[N_EDGES];
__device__ int   g_csr_src[N_EDGES];      // edges sorted by dst: src node
__device__ float g_csr_w[N_EDGES];        // per-edge norm dis[src]*dis[dst]
__device__ int   g_is64;                  // edge_index dtype flag

// ---------------- edge_index dtype detection + decode ----------------------
// JAX drops int64->int32 unless x64 is enabled; sniff the layout on device.
// int64 little-endian with values < 2^17 => every odd 32-bit word is 0.
__global__ void detect_kernel(const int* __restrict__ ei32) {
    if (blockIdx.x == 0 && threadIdx.x == 0) {
        int allzero = 1;
        #pragma unroll
        for (int i = 1; i < 128; i += 2) allzero &= (ei32[i] == 0);
        g_is64 = allzero;
    }
}

__global__ void decode_kernel(const int* __restrict__ ei32) {
    int e = blockIdx.x * blockDim.x + threadIdx.x;
    if (e >= N_EDGES) return;
    unsigned s, d;
    if (g_is64) {
        s = (unsigned)ei32[2 * e];                  // low word of int64
        d = (unsigned)ei32[2 * (N_EDGES + e)];
    } else {
        s = (unsigned)ei32[e];
        d = (unsigned)ei32[N_EDGES + e];
    }
    if (s >= N_NODES) s = 0;   // defensive clamp (prevents wild-atomic traps)
    if (d >= N_NODES) d = 0;
    g_src[e] = (int)s;
    g_dst[e] = (int)d;
}

// ---------------- CSR construction ----------------------------------------
__global__ void zero_cnt_kernel() {
    int i = blockIdx.x * blockDim.x + threadIdx.x;
    if (i < N_NODES) g_cnt[i] = 0;
}

__global__ void hist_kernel() {
    int e = blockIdx.x * blockDim.x + threadIdx.x;
    if (e < N_EDGES) atomicAdd(&g_cnt[g_dst[e]], 1);
}

__global__ void dis_kernel() {
    int i = blockIdx.x * blockDim.x + threadIdx.x;
    if (i < N_NODES) g_dis[i] = rsqrtf((float)g_cnt[i] + 1.0f);
}

// exclusive scan, stage 1: per-block (1024 elems) Hillis-Steele
__global__ void __launch_bounds__(1024) scan1_kernel() {
    __shared__ int s[1024];
    int tid = threadIdx.x;
    int i = blockIdx.x * 1024 + tid;
    int v = (i < N_NODES) ? g_cnt[i] : 0;
    s[tid] = v;
    __syncthreads();
    #pragma unroll
    for (int off = 1; off < 1024; off <<= 1) {
        int t = (tid >= off) ? s[tid - off] : 0;
        __syncthreads();
        s[tid] += t;
        __syncthreads();
    }
    if (i < N_NODES) g_rowstart[i] = s[tid] - v;          // exclusive
    if (tid == 1023) g_blocksum[blockIdx.x] = s[1023];
}

// stage 2: exclusive scan of the 98 block sums (single block)
__global__ void __launch_bounds__(128) scan2_kernel() {
    __shared__ int s[128];
    int tid = threadIdx.x;
    int v = (tid < SCAN_NB) ? g_blocksum[tid] : 0;
    s[tid] = v;
    __syncthreads();
    #pragma unroll
    for (int off = 1; off < 128; off <<= 1) {
        int t = (tid >= off) ? s[tid - off] : 0;
        __syncthreads();
        s[tid] += t;
        __syncthreads();
    }
    if (tid < SCAN_NB) g_blocksum[tid] = s[tid] - v;      // exclusive
}

// stage 3: add block offsets, init fill cursors
__global__ void scan3_kernel() {
    int i = blockIdx.x * blockDim.x + threadIdx.x;
    if (i < N_NODES) {
        int r = g_rowstart[i] + g_blocksum[i >> 10];
        g_rowstart[i] = r;
        g_fill[i] = r;
    }
}

__global__ void fill_kernel() {
    int e = blockIdx.x * blockDim.x + threadIdx.x;
    if (e < N_EDGES) {
        int s = g_src[e];
        int d = g_dst[e];
        int pos = atomicAdd(&g_fill[d], 1);
        g_csr_src[pos] = s;
        g_csr_w[pos] = g_dis[s] * g_dis[d];
    }
}

// ---------------- GEMM: h = act(in) @ W ; agg_init = h*dis^2 + b ------------
// IN_EXT:  input from ext_in param (layer 1) else g_agg (layers 2,3)
// OUT_EXT: agg-init into ext_out param (layer 3 -> d_out) else g_agg
template <int NOUT, bool RELU_IN, bool IN_EXT, bool OUT_EXT>
__global__ void __launch_bounds__(64)
gemm_kernel(const float* __restrict__ ext_in, const float* __restrict__ W,
            const float* __restrict__ b, float* __restrict__ ext_out) {
    __shared__ float xs[64 * 65];
    __shared__ float Ws[64 * NOUT];
    __shared__ float bs[NOUT];

    const float* in  = IN_EXT  ? ext_in  : g_agg;
    float*       agp = OUT_EXT ? ext_out : g_agg;

    const int tid  = threadIdx.x;
    const int base = blockIdx.x * 64;

    #pragma unroll 4
    for (int i = tid; i < 64 * NOUT; i += 64) Ws[i] = W[i];
    if (tid < NOUT) bs[tid] = b[tid];

    #pragma unroll 4
    for (int i = tid; i < 64 * 64; i += 64) {
        int node = i >> 6;
        float v = 0.0f;
        if (base + node < N_NODES) {
            v = in[(size_t)base * 64 + i];
            if (RELU_IN) v = fmaxf(v, 0.0f);
        }
        xs[node * 65 + (i & 63)] = v;
    }
    __syncthreads();

    const int gn = base + tid;
    if (gn >= N_NODES) return;

    float acc[NOUT];
    #pragma unroll
    for (int j = 0; j < NOUT; j++) acc[j] = 0.0f;

    #pragma unroll 4
    for (int k = 0; k < 64; k++) {
        float xv = xs[tid * 65 + k];
        #pragma unroll
        for (int j = 0; j < NOUT; j++) acc[j] += xv * Ws[k * NOUT + j];
    }

    float d = g_dis[gn];
    float d2 = d * d;
    float* hp = g_h + (size_t)gn * NOUT;
    float* ap = agp + (size_t)gn * NOUT;
    #pragma unroll
    for (int j = 0; j < NOUT; j += 4) {
        float4 hv = make_float4(acc[j], acc[j+1], acc[j+2], acc[j+3]);
        *(float4*)(hp + j) = hv;
        float4 av = make_float4(fmaf(hv.x, d2, bs[j]),
                                fmaf(hv.y, d2, bs[j+1]),
                                fmaf(hv.z, d2, bs[j+2]),
                                fmaf(hv.w, d2, bs[j+3]));
        *(float4*)(ap + j) = av;
    }
}

// ---------------- gather: agg[i] += sum_{j->i} w_ij * h[j] ------------------
// One warp per node, NF=64: each lane owns a float2 column slice of the row.
__global__ void __launch_bounds__(256)
gather64_kernel() {
    int node = (blockIdx.x * blockDim.x + threadIdx.x) >> 5;
    int lane = threadIdx.x & 31;
    if (node >= N_NODES) return;

    int start = g_rowstart[node];
    int n     = g_cnt[node];

    float2 acc = make_float2(0.0f, 0.0f);
    const float2* hb = (const float2*)g_h;

    int k = 0;
    for (; k + 1 < n; k += 2) {            // 2-edge unroll for MLP
        int   s0 = g_csr_src[start + k];
        float w0 = g_csr_w[start + k];
        int   s1 = g_csr_src[start + k + 1];
        float w1 = g_csr_w[start + k + 1];
        float2 v0 = hb[s0 * 32 + lane];
        float2 v1 = hb[s1 * 32 + lane];
        acc.x = fmaf(w0, v0.x, acc.x); acc.y = fmaf(w0, v0.y, acc.y);
        acc.x = fmaf(w1, v1.x, acc.x); acc.y = fmaf(w1, v1.y, acc.y);
    }
    if (k < n) {
        int   s0 = g_csr_src[start + k];
        float w0 = g_csr_w[start + k];
        float2 v0 = hb[s0 * 32 + lane];
        acc.x = fmaf(w0, v0.x, acc.x); acc.y = fmaf(w0, v0.y, acc.y);
    }

    float2* ap = (float2*)(g_agg + (size_t)node * 64) + lane;
    float2 cur = *ap;
    cur.x += acc.x; cur.y += acc.y;
    *ap = cur;
}

// NF=32: one lane per feature; accumulates into d_out (passed as arg).
__global__ void __launch_bounds__(256)
gather32_kernel(float* __restrict__ out) {
    int node = (blockIdx.x * blockDim.x + threadIdx.x) >> 5;
    int lane = threadIdx.x & 31;
    if (node >= N_NODES) return;

    int start = g_rowstart[node];
    int n     = g_cnt[node];

    float acc = 0.0f;
    int k = 0;
    for (; k + 1 < n; k += 2) {
        int   s0 = g_csr_src[start + k];
        float w0 = g_csr_w[start + k];
        int   s1 = g_csr_src[start + k + 1];
        float w1 = g_csr_w[start + k + 1];
        acc = fmaf(w0, g_h[s0 * 32 + lane], acc);
        acc = fmaf(w1, g_h[s1 * 32 + lane], acc);
    }
    if (k < n) {
        int   s0 = g_csr_src[start + k];
        float w0 = g_csr_w[start + k];
        acc = fmaf(w0, g_h[s0 * 32 + lane], acc);
    }

    out[(size_t)node * 32 + lane] += acc;
}

// ---------------- launch --------------------------------------------------
extern "C" void kernel_launch(void* const* d_in, const int* in_sizes, int n_in,
                              void* d_out, int out_size) {
    const float* x    = (const float*)d_in[0];
    const int*   ei32 = (const int*)d_in[1];   // int32 OR int64 (auto-detected)
    const float* W1 = (const float*)d_in[2];
    const float* b1 = (const float*)d_in[3];
    const float* W2 = (const float*)d_in[4];
    const float* b2 = (const float*)d_in[5];
    const float* W3 = (const float*)d_in[6];
    const float* b3 = (const float*)d_in[7];
    float* out = (float*)d_out;

    const int TPB = 256;
    const int eb  = (N_EDGES + TPB - 1) / TPB;
    const int nb  = (N_NODES + TPB - 1) / TPB;
    const int gemm_blocks   = (N_NODES + 63) / 64;
    const int gather_blocks = (N_NODES * 32 + TPB - 1) / TPB;  // 1 warp/node

    // Decode edges (dtype-robust), build CSR — all device-side, capturable.
    detect_kernel<<<1, 32>>>(ei32);
    decode_kernel<<<eb, TPB>>>(ei32);
    zero_cnt_kernel<<<nb, TPB>>>();
    hist_kernel<<<eb, TPB>>>();
    dis_kernel<<<nb, TPB>>>();
    scan1_kernel<<<SCAN_NB, 1024>>>();
    scan2_kernel<<<1, 128>>>();
    scan3_kernel<<<nb, TPB>>>();
    fill_kernel<<<eb, TPB>>>();

    // Layer 1: h = x@W1 ; g_agg = h*dis^2 + b1 ; gather adds neighbor sums
    gemm_kernel<64, false, true, false><<<gemm_blocks, 64>>>(x, W1, b1, nullptr);
    gather64_kernel<<<gather_blocks, TPB>>>();
    // Layer 2: in = relu(g_agg) (block-local in-place safe)
    gemm_kernel<64, true, false, false><<<gemm_blocks, 64>>>(nullptr, W2, b2, nullptr);
    gather64_kernel<<<gather_blocks, TPB>>>();
    // Layer 3: NOUT=32, agg-init written straight into d_out
    gemm_kernel<32, true, false, true><<<gemm_blocks, 64>>>(nullptr, W3, b3, out);
    gather32_kernel<<<gather_blocks, TPB>>>(out);
}

// round 5
// speedup vs baseline: 1.0546x; 1.0546x over previous
#include <cuda_runtime.h>
#include <math.h>

#define N_NODES 100000
#define N_EDGES 1600000
#define SCAN_NB ((N_NODES + 1023) / 1024)   // 98 blocks

// ---------------- scratch (device globals: no allocation allowed) ----------
__device__ __align__(16) float g_h[N_NODES * 64];    // h = act(X) @ W (raw)
__device__ __align__(16) float g_agg[N_NODES * 64];  // aggregation buffer
__device__ float g_dis[N_NODES];          // rsqrt(deg+1)
__device__ int   g_cnt[N_NODES];          // in-degree (by dst)
__device__ int   g_rowstart[N_NODES];     // CSR row offsets (exclusive scan)
__device__ int   g_fill[N_NODES];         // atomic fill cursors
__device__ int   g_blocksum[SCAN_NB];
__device__ __align__(16) int2 g_csr[N_EDGES];  // (src, __float_as_int(w)) by dst
__device__ int   g_is64;                  // edge_index dtype flag

// ---------------- dtype detect + zero counters ------------------------------
// JAX may keep edge_index int64 or silently use int32; sniff layout on device.
// int64 LE with values < 2^17 => every odd 32-bit word is 0.
__global__ void zero_detect_kernel(const int* __restrict__ ei32) {
    int i = blockIdx.x * blockDim.x + threadIdx.x;
    if (i < N_NODES) g_cnt[i] = 0;
    if (i == 0) {
        int allzero = 1;
        #pragma unroll
        for (int j = 1; j < 128; j += 2) allzero &= (ei32[j] == 0);
        g_is64 = allzero;
    }
}

__device__ __forceinline__ unsigned load_idx(const int* ei32, long long pos, int is64) {
    unsigned v = is64 ? (unsigned)ei32[2 * pos] : (unsigned)ei32[pos];
    return (v >= N_NODES) ? 0u : v;   // defensive clamp
}

__global__ void hist_kernel(const int* __restrict__ ei32) {
    int e = blockIdx.x * blockDim.x + threadIdx.x;
    if (e < N_EDGES) {
        unsigned d = load_idx(ei32, (long long)N_EDGES + e, g_is64);
        atomicAdd(&g_cnt[d], 1);
    }
}

// exclusive scan stage 1 (per 1024 block) + dis = rsqrt(deg+1)
__global__ void __launch_bounds__(1024) scan1_kernel() {
    __shared__ int s[1024];
    int tid = threadIdx.x;
    int i = blockIdx.x * 1024 + tid;
    int v = (i < N_NODES) ? g_cnt[i] : 0;
    s[tid] = v;
    __syncthreads();
    #pragma unroll
    for (int off = 1; off < 1024; off <<= 1) {
        int t = (tid >= off) ? s[tid - off] : 0;
        __syncthreads();
        s[tid] += t;
        __syncthreads();
    }
    if (i < N_NODES) {
        g_rowstart[i] = s[tid] - v;                  // exclusive
        g_dis[i] = rsqrtf((float)v + 1.0f);
    }
    if (tid == 1023) g_blocksum[blockIdx.x] = s[1023];
}

__global__ void __launch_bounds__(128) scan2_kernel() {
    __shared__ int s[128];
    int tid = threadIdx.x;
    int v = (tid < SCAN_NB) ? g_blocksum[tid] : 0;
    s[tid] = v;
    __syncthreads();
    #pragma unroll
    for (int off = 1; off < 128; off <<= 1) {
        int t = (tid >= off) ? s[tid - off] : 0;
        __syncthreads();
        s[tid] += t;
        __syncthreads();
    }
    if (tid < SCAN_NB) g_blocksum[tid] = s[tid] - v;      // exclusive
}

__global__ void scan3_kernel() {
    int i = blockIdx.x * blockDim.x + threadIdx.x;
    if (i < N_NODES) {
        int r = g_rowstart[i] + g_blocksum[i >> 10];
        g_rowstart[i] = r;
        g_fill[i] = r;
    }
}

// fill CSR directly from edge_index: (src, w) interleaved int2
__global__ void fill_kernel(const int* __restrict__ ei32) {
    int e = blockIdx.x * blockDim.x + threadIdx.x;
    if (e < N_EDGES) {
        int is64 = g_is64;
        unsigned s = load_idx(ei32, e, is64);
        unsigned d = load_idx(ei32, (long long)N_EDGES + e, is64);
        float w = g_dis[s] * g_dis[d];
        int pos = atomicAdd(&g_fill[d], 1);
        g_csr[pos] = make_int2((int)s, __float_as_int(w));
    }
}

// ---------------- GEMM: h = act(in) @ W ; agg_init = h*dis^2 + b ------------
template <int NOUT, bool RELU_IN, bool IN_EXT, bool OUT_EXT>
__global__ void __launch_bounds__(64)
gemm_kernel(const float* __restrict__ ext_in, const float* __restrict__ W,
            const float* __restrict__ b, float* __restrict__ ext_out) {
    __shared__ float xs[64 * 65];
    __shared__ float Ws[64 * NOUT];
    __shared__ float bs[NOUT];

    const float* in  = IN_EXT  ? ext_in  : g_agg;
    float*       agp = OUT_EXT ? ext_out : g_agg;

    const int tid  = threadIdx.x;
    const int base = blockIdx.x * 64;

    #pragma unroll 4
    for (int i = tid; i < 64 * NOUT; i += 64) Ws[i] = W[i];
    if (tid < NOUT) bs[tid] = b[tid];

    #pragma unroll 4
    for (int i = tid; i < 64 * 64; i += 64) {
        int node = i >> 6;
        float v = 0.0f;
        if (base + node < N_NODES) {
            v = in[(size_t)base * 64 + i];
            if (RELU_IN) v = fmaxf(v, 0.0f);
        }
        xs[node * 65 + (i & 63)] = v;
    }
    __syncthreads();

    const int gn = base + tid;
    if (gn >= N_NODES) return;

    float acc[NOUT];
    #pragma unroll
    for (int j = 0; j < NOUT; j++) acc[j] = 0.0f;

    #pragma unroll 4
    for (int k = 0; k < 64; k++) {
        float xv = xs[tid * 65 + k];
        #pragma unroll
        for (int j = 0; j < NOUT; j++) acc[j] += xv * Ws[k * NOUT + j];
    }

    float d = g_dis[gn];
    float d2 = d * d;
    float* hp = g_h + (size_t)gn * NOUT;
    float* ap = agp + (size_t)gn * NOUT;
    #pragma unroll
    for (int j = 0; j < NOUT; j += 4) {
        float4 hv = make_float4(acc[j], acc[j+1], acc[j+2], acc[j+3]);
        *(float4*)(hp + j) = hv;
        float4 av = make_float4(fmaf(hv.x, d2, bs[j]),
                                fmaf(hv.y, d2, bs[j+1]),
                                fmaf(hv.z, d2, bs[j+2]),
                                fmaf(hv.w, d2, bs[j+3]));
        *(float4*)(ap + j) = av;
    }
}

// ---------------- gather: agg[i] += sum_{j->i} w_ij * h[j] ------------------
// NF=64: warp per node; half-warp (16 lanes x float4) per edge, 2 edges in
// flight. Partial sums combined via shfl at the end.
__global__ void __launch_bounds__(256)
gather64_kernel() {
    int node = (blockIdx.x * blockDim.x + threadIdx.x) >> 5;
    if (node >= N_NODES) return;
    int lane = threadIdx.x & 31;
    int half = lane >> 4;          // which edge parity this lane works on
    int l16  = lane & 15;          // float4 chunk within the 64-float row

    int start = g_rowstart[node];
    int n     = g_cnt[node];

    float4 acc = make_float4(0.f, 0.f, 0.f, 0.f);
    const float4* hb = (const float4*)g_h;

    #pragma unroll 2
    for (int k = half; k < n; k += 2) {
        int2  sw = g_csr[start + k];
        float w  = __int_as_float(sw.y);
        float4 v = hb[(size_t)sw.x * 16 + l16];
        acc.x = fmaf(w, v.x, acc.x);
        acc.y = fmaf(w, v.y, acc.y);
        acc.z = fmaf(w, v.z, acc.z);
        acc.w = fmaf(w, v.w, acc.w);
    }

    acc.x += __shfl_down_sync(0xffffffffu, acc.x, 16);
    acc.y += __shfl_down_sync(0xffffffffu, acc.y, 16);
    acc.z += __shfl_down_sync(0xffffffffu, acc.z, 16);
    acc.w += __shfl_down_sync(0xffffffffu, acc.w, 16);

    if (half == 0) {
        float4* ap = (float4*)(g_agg + (size_t)node * 64) + l16;
        float4 cur = *ap;
        cur.x += acc.x; cur.y += acc.y; cur.z += acc.z; cur.w += acc.w;
        *ap = cur;
    }
}

// NF=32: warp per node; quarter-warp (8 lanes x float4) per edge, 4 in flight.
__global__ void __launch_bounds__(256)
gather32_kernel(float* __restrict__ out) {
    int node = (blockIdx.x * blockDim.x + threadIdx.x) >> 5;
    if (node >= N_NODES) return;
    int lane = threadIdx.x & 31;
    int q    = lane >> 3;          // edge slot 0..3
    int l8   = lane & 7;           // float4 chunk within the 32-float row

    int start = g_rowstart[node];
    int n     = g_cnt[node];

    float4 acc = make_float4(0.f, 0.f, 0.f, 0.f);
    const float4* hb = (const float4*)g_h;

    #pragma unroll 2
    for (int k = q; k < n; k += 4) {
        int2  sw = g_csr[start + k];
        float w  = __int_as_float(sw.y);
        float4 v = hb[(size_t)sw.x * 8 + l8];
        acc.x = fmaf(w, v.x, acc.x);
        acc.y = fmaf(w, v.y, acc.y);
        acc.z = fmaf(w, v.z, acc.z);
        acc.w = fmaf(w, v.w, acc.w);
    }

    acc.x += __shfl_down_sync(0xffffffffu, acc.x, 16);
    acc.y += __shfl_down_sync(0xffffffffu, acc.y, 16);
    acc.z += __shfl_down_sync(0xffffffffu, acc.z, 16);
    acc.w += __shfl_down_sync(0xffffffffu, acc.w, 16);
    acc.x += __shfl_down_sync(0xffffffffu, acc.x, 8);
    acc.y += __shfl_down_sync(0xffffffffu, acc.y, 8);
    acc.z += __shfl_down_sync(0xffffffffu, acc.z, 8);
    acc.w += __shfl_down_sync(0xffffffffu, acc.w, 8);

    if (q == 0) {
        float4* ap = (float4*)(out + (size_t)node * 32) + l8;
        float4 cur = *ap;
        cur.x += acc.x; cur.y += acc.y; cur.z += acc.z; cur.w += acc.w;
        *ap = cur;
    }
}

// ---------------- launch --------------------------------------------------
extern "C" void kernel_launch(void* const* d_in, const int* in_sizes, int n_in,
                              void* d_out, int out_size) {
    const float* x    = (const float*)d_in[0];
    const int*   ei32 = (const int*)d_in[1];   // int32 OR int64 (auto-detected)
    const float* W1 = (const float*)d_in[2];
    const float* b1 = (const float*)d_in[3];
    const float* W2 = (const float*)d_in[4];
    const float* b2 = (const float*)d_in[5];
    const float* W3 = (const float*)d_in[6];
    const float* b3 = (const float*)d_in[7];
    float* out = (float*)d_out;

    const int TPB = 256;
    const int eb  = (N_EDGES + TPB - 1) / TPB;
    const int nb  = (N_NODES + TPB - 1) / TPB;
    const int gemm_blocks   = (N_NODES + 63) / 64;
    const int gather_blocks = (N_NODES * 32 + TPB - 1) / TPB;  // 1 warp/node

    // CSR build — all device-side, graph-capturable
    zero_detect_kernel<<<nb, TPB>>>(ei32);
    hist_kernel<<<eb, TPB>>>(ei32);
    scan1_kernel<<<SCAN_NB, 1024>>>();
    scan2_kernel<<<1, 128>>>();
    scan3_kernel<<<nb, TPB>>>();
    fill_kernel<<<eb, TPB>>>(ei32);

    // Layer 1: h = x@W1 ; g_agg = h*dis^2 + b1 ; gather adds neighbor sums
    gemm_kernel<64, false, true, false><<<gemm_blocks, 64>>>(x, W1, b1, nullptr);
    gather64_kernel<<<gather_blocks, TPB>>>();
    // Layer 2: in = relu(g_agg) (block-local in-place safe)
    gemm_kernel<64, true, false, false><<<gemm_blocks, 64>>>(nullptr, W2, b2, nullptr);
    gather64_kernel<<<gather_blocks, TPB>>>();
    // Layer 3: NOUT=32, agg-init written straight into d_out
    gemm_kernel<32, true, false, true><<<gemm_blocks, 64>>>(nullptr, W3, b3, out);
    gather32_kernel<<<gather_blocks, TPB>>>(out);
}

// round 6
// speedup vs baseline: 1.3840x; 1.3124x over previous
#include <cuda_runtime.h>
#include <math.h>

#define N_NODES 100000
#define N_EDGES 1600000
#define SCAN_NB ((N_NODES + 1023) / 1024)   // 98 blocks

// ---------------- scratch (device globals: no allocation allowed) ----------
__device__ __align__(16) float g_h[N_NODES * 64];    // h = act(in) @ W
__device__ __align__(16) float g_agg[N_NODES * 64];  // aggregation buffer
__device__ float g_dis[N_NODES];              // rsqrt(deg+1)
__device__ int   g_cnt[N_NODES];              // in-degree; re-zeroed by scan1
__device__ int   g_rowstart[N_NODES + 1];     // CSR row offsets
__device__ int   g_fill[N_NODES];             // atomic fill cursors
__device__ int   g_blocksum[SCAN_NB];
__device__ __align__(16) int2 g_csr[N_EDGES]; // (src, bits(w)) sorted by dst
__device__ int   g_is64;                      // edge_index dtype flag

// ---------------- helpers ---------------------------------------------------
__device__ __forceinline__ unsigned load_idx(const int* ei32, long long pos, int is64) {
    unsigned v = is64 ? (unsigned)ei32[2 * pos] : (unsigned)ei32[pos];
    return (v >= N_NODES) ? 0u : v;   // defensive clamp
}

// ---------------- GEMM: g_h = act(in) @ W -----------------------------------
// 128 threads, 128 nodes/block. Thread (tx,ty) computes 4 nodes (tx+32i) x
// JT cols (ty*JT..). Inner k: 4 x-LDS (conflict-free) + JT W-LDS (broadcast),
// 4*JT FFMA -> FFMA-pipe bound. DETECT: block 0 also sniffs edge dtype
// (JAX int64 LE with ids < 2^17 => odd words all zero).
template <int NOUT, bool RELU_IN, bool IN_EXT, bool DETECT>
__global__ void __launch_bounds__(128)
gemm_kernel(const float* __restrict__ ext_in, const float* __restrict__ W,
            const int* __restrict__ ei32) {
    constexpr int JT = NOUT / 4;          // 16 (NOUT=64) or 8 (NOUT=32)
    __shared__ float xs[64 * 129];        // xs[k*129 + node]
    __shared__ float Ws[64 * NOUT];

    const int tid  = threadIdx.x;
    const int base = blockIdx.x * 128;
    const float* in = IN_EXT ? ext_in : g_agg;

    if (DETECT && blockIdx.x == 0 && tid == 0) {
        int allzero = 1;
        #pragma unroll
        for (int j = 1; j < 128; j += 2) allzero &= (ei32[j] == 0);
        g_is64 = allzero;
    }

    #pragma unroll 4
    for (int i = tid; i < 64 * NOUT; i += 128) Ws[i] = W[i];

    // load + transpose 128x64 input tile into smem (k-major, stride 129)
    #pragma unroll 8
    for (int idx = tid; idx < 128 * 64; idx += 128) {
        int node = idx >> 6, k = idx & 63;
        float v = 0.0f;
        if (base + node < N_NODES) {
            v = in[(size_t)(base + node) * 64 + k];
            if (RELU_IN) v = fmaxf(v, 0.0f);
        }
        xs[k * 129 + node] = v;
    }
    __syncthreads();

    const int tx = tid & 31;
    const int ty = tid >> 5;              // warp id 0..3
    const int col0 = ty * JT;

    float acc[4][JT];
    #pragma unroll
    for (int i = 0; i < 4; i++)
        #pragma unroll
        for (int j = 0; j < JT; j++) acc[i][j] = 0.0f;

    #pragma unroll 4
    for (int k = 0; k < 64; k++) {
        float xv[4];
        #pragma unroll
        for (int i = 0; i < 4; i++) xv[i] = xs[k * 129 + tx + 32 * i];
        float wv[JT];
        #pragma unroll
        for (int j = 0; j < JT; j++) wv[j] = Ws[k * NOUT + col0 + j];
        #pragma unroll
        for (int i = 0; i < 4; i++)
            #pragma unroll
            for (int j = 0; j < JT; j++)
                acc[i][j] = fmaf(xv[i], wv[j], acc[i][j]);
    }

    #pragma unroll
    for (int i = 0; i < 4; i++) {
        int node = base + tx + 32 * i;
        if (node < N_NODES) {
            float* hp = g_h + (size_t)node * NOUT + col0;
            #pragma unroll
            for (int j = 0; j < JT; j += 4)
                *(float4*)(hp + j) = make_float4(acc[i][j], acc[i][j+1],
                                                 acc[i][j+2], acc[i][j+3]);
        }
    }
}

// ---------------- CSR build -------------------------------------------------
__global__ void hist_kernel(const int* __restrict__ ei32) {
    int e = blockIdx.x * blockDim.x + threadIdx.x;
    if (e < N_EDGES) {
        unsigned d = load_idx(ei32, (long long)N_EDGES + e, g_is64);
        atomicAdd(&g_cnt[d], 1);
    }
}

// per-1024-block exclusive scan + dis + RE-ZERO g_cnt (invariant for replays)
__global__ void __launch_bounds__(1024) scan1_kernel() {
    __shared__ int s[1024];
    int tid = threadIdx.x;
    int i = blockIdx.x * 1024 + tid;
    int v = (i < N_NODES) ? g_cnt[i] : 0;
    s[tid] = v;
    __syncthreads();
    #pragma unroll
    for (int off = 1; off < 1024; off <<= 1) {
        int t = (tid >= off) ? s[tid - off] : 0;
        __syncthreads();
        s[tid] += t;
        __syncthreads();
    }
    if (i < N_NODES) {
        g_rowstart[i] = s[tid] - v;                  // partial exclusive
        g_dis[i] = rsqrtf((float)v + 1.0f);
        g_cnt[i] = 0;                                // restore zero invariant
    }
    if (tid == 1023) g_blocksum[blockIdx.x] = s[1023];
}

// fused: add prefix of blocksums (<=98 values, recomputed per block) + fill init
__global__ void __launch_bounds__(1024) scan23_kernel() {
    __shared__ int s[128];
    int tid = threadIdx.x;
    if (tid < 128) s[tid] = (tid < (int)blockIdx.x && tid < SCAN_NB) ? g_blocksum[tid] : 0;
    __syncthreads();
    #pragma unroll
    for (int o = 64; o > 0; o >>= 1) {
        if (tid < o) s[tid] += s[tid + o];
        __syncthreads();
    }
    int offset = s[0];
    int i = blockIdx.x * 1024 + tid;
    if (i < N_NODES) {
        int r = g_rowstart[i] + offset;
        g_rowstart[i] = r;
        g_fill[i] = r;
    }
    if (blockIdx.x == 0 && tid == 0) g_rowstart[N_NODES] = N_EDGES;
}

__global__ void fill_kernel(const int* __restrict__ ei32) {
    int e = blockIdx.x * blockDim.x + threadIdx.x;
    if (e < N_EDGES) {
        int is64 = g_is64;
        unsigned sn = load_idx(ei32, e, is64);
        unsigned dn = load_idx(ei32, (long long)N_EDGES + e, is64);
        float w = g_dis[sn] * g_dis[dn];
        int pos = atomicAdd(&g_fill[dn], 1);
        g_csr[pos] = make_int2((int)sn, __float_as_int(w));
    }
}

// ---------------- gather: agg[i] = sum_j w*h[j] + dis^2*h[i] + b -------------
// NF=64: warp/node; each half-warp (16 lanes x float4) streams 2 edges per
// iteration -> 4 independent h-row loads in flight per warp.
__global__ void __launch_bounds__(256)
gather64_kernel(const float* __restrict__ b) {
    int node = (blockIdx.x * blockDim.x + threadIdx.x) >> 5;
    if (node >= N_NODES) return;
    int lane = threadIdx.x & 31;
    int half = lane >> 4;
    int l16  = lane & 15;

    int start = g_rowstart[node];
    int end   = g_rowstart[node + 1];

    float4 a0 = make_float4(0.f, 0.f, 0.f, 0.f);
    float4 a1 = make_float4(0.f, 0.f, 0.f, 0.f);
    const float4* hb = (const float4*)g_h;

    int k = start + half * 2;
    #pragma unroll 2
    for (; k + 1 < end; k += 4) {
        int2 e0 = g_csr[k];
        int2 e1 = g_csr[k + 1];
        float w0 = __int_as_float(e0.y), w1 = __int_as_float(e1.y);
        float4 v0 = hb[(size_t)e0.x * 16 + l16];
        float4 v1 = hb[(size_t)e1.x * 16 + l16];
        a0.x = fmaf(w0, v0.x, a0.x); a0.y = fmaf(w0, v0.y, a0.y);
        a0.z = fmaf(w0, v0.z, a0.z); a0.w = fmaf(w0, v0.w, a0.w);
        a1.x = fmaf(w1, v1.x, a1.x); a1.y = fmaf(w1, v1.y, a1.y);
        a1.z = fmaf(w1, v1.z, a1.z); a1.w = fmaf(w1, v1.w, a1.w);
    }
    if (k < end) {
        int2 e0 = g_csr[k];
        float w0 = __int_as_float(e0.y);
        float4 v0 = hb[(size_t)e0.x * 16 + l16];
        a0.x = fmaf(w0, v0.x, a0.x); a0.y = fmaf(w0, v0.y, a0.y);
        a0.z = fmaf(w0, v0.z, a0.z); a0.w = fmaf(w0, v0.w, a0.w);
    }
    a0.x += a1.x; a0.y += a1.y; a0.z += a1.z; a0.w += a1.w;

    a0.x += __shfl_down_sync(0xffffffffu, a0.x, 16);
    a0.y += __shfl_down_sync(0xffffffffu, a0.y, 16);
    a0.z += __shfl_down_sync(0xffffffffu, a0.z, 16);
    a0.w += __shfl_down_sync(0xffffffffu, a0.w, 16);

    if (half == 0) {
        float d  = g_dis[node];
        float d2 = d * d;
        float4 hs = hb[(size_t)node * 16 + l16];
        float4 bv = ((const float4*)b)[l16];
        float4 o;
        o.x = fmaf(d2, hs.x, a0.x) + bv.x;
        o.y = fmaf(d2, hs.y, a0.y) + bv.y;
        o.z = fmaf(d2, hs.z, a0.z) + bv.z;
        o.w = fmaf(d2, hs.w, a0.w) + bv.w;
        ((float4*)(g_agg + (size_t)node * 64))[l16] = o;
    }
}

// NF=32: quarter-warp (8 lanes x float4) per edge stream, 4 streams in flight;
// writes final output (init + neighbors + self + bias) straight to d_out.
__global__ void __launch_bounds__(256)
gather32_kernel(const float* __restrict__ b, float* __restrict__ out) {
    int node = (blockIdx.x * blockDim.x + threadIdx.x) >> 5;
    if (node >= N_NODES) return;
    int lane = threadIdx.x & 31;
    int q  = lane >> 3;
    int l8 = lane & 7;

    int start = g_rowstart[node];
    int end   = g_rowstart[node + 1];

    float4 acc = make_float4(0.f, 0.f, 0.f, 0.f);
    const float4* hb = (const float4*)g_h;

    #pragma unroll 2
    for (int k = start + q; k < end; k += 4) {
        int2 e = g_csr[k];
        float w = __int_as_float(e.y);
        float4 v = hb[(size_t)e.x * 8 + l8];
        acc.x = fmaf(w, v.x, acc.x); acc.y = fmaf(w, v.y, acc.y);
        acc.z = fmaf(w, v.z, acc.z); acc.w = fmaf(w, v.w, acc.w);
    }

    acc.x += __shfl_down_sync(0xffffffffu, acc.x, 16);
    acc.y += __shfl_down_sync(0xffffffffu, acc.y, 16);
    acc.z += __shfl_down_sync(0xffffffffu, acc.z, 16);
    acc.w += __shfl_down_sync(0xffffffffu, acc.w, 16);
    acc.x += __shfl_down_sync(0xffffffffu, acc.x, 8);
    acc.y += __shfl_down_sync(0xffffffffu, acc.y, 8);
    acc.z += __shfl_down_sync(0xffffffffu, acc.z, 8);
    acc.w += __shfl_down_sync(0xffffffffu, acc.w, 8);

    if (q == 0) {
        float d  = g_dis[node];
        float d2 = d * d;
        float4 hs = hb[(size_t)node * 8 + l8];
        float4 bv = ((const float4*)b)[l8];
        float4 o;
        o.x = fmaf(d2, hs.x, acc.x) + bv.x;
        o.y = fmaf(d2, hs.y, acc.y) + bv.y;
        o.z = fmaf(d2, hs.z, acc.z) + bv.z;
        o.w = fmaf(d2, hs.w, acc.w) + bv.w;
        ((float4*)(out + (size_t)node * 32))[l8] = o;
    }
}

// ---------------- launch -----------------------------------------------------
extern "C" void kernel_launch(void* const* d_in, const int* in_sizes, int n_in,
                              void* d_out, int out_size) {
    const float* x    = (const float*)d_in[0];
    const int*   ei32 = (const int*)d_in[1];   // int32 OR int64 (auto-detected)
    const float* W1 = (const float*)d_in[2];
    const float* b1 = (const float*)d_in[3];
    const float* W2 = (const float*)d_in[4];
    const float* b2 = (const float*)d_in[5];
    const float* W3 = (const float*)d_in[6];
    const float* b3 = (const float*)d_in[7];
    float* out = (float*)d_out;

    const int TPB = 256;
    const int eb  = (N_EDGES + TPB - 1) / TPB;
    const int gemm_blocks   = (N_NODES + 127) / 128;
    const int gather_blocks = (N_NODES * 32 + TPB - 1) / TPB;  // 1 warp/node

    // launch 0: gemm1 (h = x@W1) + dtype detect
    gemm_kernel<64, false, true, true><<<gemm_blocks, 128>>>(x, W1, ei32);
    // launches 1-4: CSR build (g_cnt zero-on-entry invariant kept by scan1)
    hist_kernel<<<eb, TPB>>>(ei32);
    scan1_kernel<<<SCAN_NB, 1024>>>();
    scan23_kernel<<<SCAN_NB, 1024>>>();
    fill_kernel<<<eb, TPB>>>(ei32);
    // launch 5 (profiled): layer-1 gather
    gather64_kernel<<<gather_blocks, TPB>>>(b1);
    // layer 2
    gemm_kernel<64, true, false, false><<<gemm_blocks, 128>>>(nullptr, W2, ei32);
    gather64_kernel<<<gather_blocks, TPB>>>(b2);
    // layer 3
    gemm_kernel<32, true, false, false><<<gemm_blocks, 128>>>(nullptr, W3, ei32);
    gather32_kernel<<<gather_blocks, TPB>>>(b3, out);
}

// round 7
// speedup vs baseline: 1.4428x; 1.0425x over previous
#include <cuda_runtime.h>
#include <cuda_fp16.h>
#include <math.h>

#define N_NODES 100000
#define N_EDGES 1600000
#define SCAN_NB ((N_NODES + 1023) / 1024)   // 98 blocks

// ---------------- scratch (device globals: no allocation allowed) ----------
__device__ __align__(16) __half g_h[N_NODES * 64];   // h = act(in)@W, fp16
__device__ __align__(16) float  g_agg[N_NODES * 64]; // aggregation (fp32)
__device__ float g_dis[N_NODES];              // rsqrt(deg+1)
__device__ int   g_cnt[N_NODES];              // in-degree; re-zeroed by scan1
__device__ int   g_rowstart[N_NODES + 1];     // CSR row offsets
__device__ int   g_fill[N_NODES];             // atomic fill cursors
__device__ int   g_blocksum[SCAN_NB];
__device__ __align__(16) int2 g_csr[N_EDGES]; // (src, bits(w)) sorted by dst
__device__ int   g_is64;                      // edge_index dtype flag

// ---------------- helpers ---------------------------------------------------
__device__ __forceinline__ unsigned load_idx(const int* ei32, long long pos, int is64) {
    unsigned v = is64 ? (unsigned)ei32[2 * pos] : (unsigned)ei32[pos];
    return (v >= N_NODES) ? 0u : v;   // defensive clamp
}

// ---------------- GEMM: g_h = act(in) @ W  (fp32 compute, fp16 store) -------
// 128 threads, 128 nodes/block; thread (tx,ty): 4 nodes x JT cols.
template <int NOUT, bool RELU_IN, bool IN_EXT, bool DETECT>
__global__ void __launch_bounds__(128)
gemm_kernel(const float* __restrict__ ext_in, const float* __restrict__ W,
            const int* __restrict__ ei32) {
    constexpr int JT = NOUT / 4;          // 16 (NOUT=64) or 8 (NOUT=32)
    __shared__ float xs[64 * 129];        // xs[k*129 + node]
    __shared__ float Ws[64 * NOUT];

    const int tid  = threadIdx.x;
    const int base = blockIdx.x * 128;
    const float* in = IN_EXT ? ext_in : g_agg;

    if (DETECT && blockIdx.x == 0 && tid == 0) {
        int allzero = 1;
        #pragma unroll
        for (int j = 1; j < 128; j += 2) allzero &= (ei32[j] == 0);
        g_is64 = allzero;
    }

    #pragma unroll 4
    for (int i = tid; i < 64 * NOUT; i += 128) Ws[i] = W[i];

    #pragma unroll 8
    for (int idx = tid; idx < 128 * 64; idx += 128) {
        int node = idx >> 6, k = idx & 63;
        float v = 0.0f;
        if (base + node < N_NODES) {
            v = in[(size_t)(base + node) * 64 + k];
            if (RELU_IN) v = fmaxf(v, 0.0f);
        }
        xs[k * 129 + node] = v;
    }
    __syncthreads();

    const int tx = tid & 31;
    const int ty = tid >> 5;
    const int col0 = ty * JT;

    float acc[4][JT];
    #pragma unroll
    for (int i = 0; i < 4; i++)
        #pragma unroll
        for (int j = 0; j < JT; j++) acc[i][j] = 0.0f;

    #pragma unroll 4
    for (int k = 0; k < 64; k++) {
        float xv[4];
        #pragma unroll
        for (int i = 0; i < 4; i++) xv[i] = xs[k * 129 + tx + 32 * i];
        float wv[JT];
        #pragma unroll
        for (int j = 0; j < JT; j++) wv[j] = Ws[k * NOUT + col0 + j];
        #pragma unroll
        for (int i = 0; i < 4; i++)
            #pragma unroll
            for (int j = 0; j < JT; j++)
                acc[i][j] = fmaf(xv[i], wv[j], acc[i][j]);
    }

    #pragma unroll
    for (int i = 0; i < 4; i++) {
        int node = base + tx + 32 * i;
        if (node < N_NODES) {
            // pack JT fp32 -> JT/2 half2 -> uint4 stores (16B aligned)
            uint4 pk[JT / 8];
            unsigned* pw = (unsigned*)pk;
            #pragma unroll
            for (int j = 0; j < JT; j += 2) {
                __half2 h2 = __floats2half2_rn(acc[i][j], acc[i][j + 1]);
                pw[j / 2] = *(unsigned*)&h2;
            }
            uint4* dst = (uint4*)(g_h + (size_t)node * NOUT + col0);
            #pragma unroll
            for (int c = 0; c < JT / 8; c++) dst[c] = pk[c];
        }
    }
}

// ---------------- CSR build -------------------------------------------------
__global__ void hist_kernel(const int* __restrict__ ei32) {
    int e = blockIdx.x * blockDim.x + threadIdx.x;
    if (e < N_EDGES) {
        unsigned d = load_idx(ei32, (long long)N_EDGES + e, g_is64);
        atomicAdd(&g_cnt[d], 1);
    }
}

__global__ void __launch_bounds__(1024) scan1_kernel() {
    __shared__ int s[1024];
    int tid = threadIdx.x;
    int i = blockIdx.x * 1024 + tid;
    int v = (i < N_NODES) ? g_cnt[i] : 0;
    s[tid] = v;
    __syncthreads();
    #pragma unroll
    for (int off = 1; off < 1024; off <<= 1) {
        int t = (tid >= off) ? s[tid - off] : 0;
        __syncthreads();
        s[tid] += t;
        __syncthreads();
    }
    if (i < N_NODES) {
        g_rowstart[i] = s[tid] - v;                  // partial exclusive
        g_dis[i] = rsqrtf((float)v + 1.0f);
        g_cnt[i] = 0;                                // restore zero invariant
    }
    if (tid == 1023) g_blocksum[blockIdx.x] = s[1023];
}

__global__ void __launch_bounds__(1024) scan23_kernel() {
    __shared__ int s[128];
    int tid = threadIdx.x;
    if (tid < 128) s[tid] = (tid < (int)blockIdx.x && tid < SCAN_NB) ? g_blocksum[tid] : 0;
    __syncthreads();
    #pragma unroll
    for (int o = 64; o > 0; o >>= 1) {
        if (tid < o) s[tid] += s[tid + o];
        __syncthreads();
    }
    int offset = s[0];
    int i = blockIdx.x * 1024 + tid;
    if (i < N_NODES) {
        int r = g_rowstart[i] + offset;
        g_rowstart[i] = r;
        g_fill[i] = r;
    }
    if (blockIdx.x == 0 && tid == 0) g_rowstart[N_NODES] = N_EDGES;
}

__global__ void fill_kernel(const int* __restrict__ ei32) {
    int e = blockIdx.x * blockDim.x + threadIdx.x;
    if (e < N_EDGES) {
        int is64 = g_is64;
        unsigned sn = load_idx(ei32, e, is64);
        unsigned dn = load_idx(ei32, (long long)N_EDGES + e, is64);
        float w = g_dis[sn] * g_dis[dn];
        int pos = atomicAdd(&g_fill[dn], 1);
        g_csr[pos] = make_int2((int)sn, __float_as_int(w));
    }
}

// ---------------- gather: agg[i] = sum_j w*h[j] + dis^2*h[i] + b -------------
// NF=64: warp/node; quarter-warp (8 lanes x uint4 = 128B fp16 row) per edge,
// 4 edge streams in flight; fp32 accumulate; epilogue fuses self-loop + bias.
__global__ void __launch_bounds__(256)
gather64_kernel(const float* __restrict__ b) {
    int node = (blockIdx.x * blockDim.x + threadIdx.x) >> 5;
    if (node >= N_NODES) return;
    int lane = threadIdx.x & 31;
    int q  = lane >> 3;           // edge stream 0..3
    int l8 = lane & 7;            // 16B chunk within 128B row

    int start = g_rowstart[node];
    int end   = g_rowstart[node + 1];

    float acc[8];
    #pragma unroll
    for (int t = 0; t < 8; t++) acc[t] = 0.0f;
    const uint4* hb = (const uint4*)g_h;   // 8 uint4 per 64-col row

    for (int k = start + q; k < end; k += 4) {
        int2 e = g_csr[k];
        float w = __int_as_float(e.y);
        uint4 v = hb[(size_t)e.x * 8 + l8];
        const __half2* hp = (const __half2*)&v;
        #pragma unroll
        for (int t = 0; t < 4; t++) {
            float2 f = __half22float2(hp[t]);
            acc[2 * t]     = fmaf(w, f.x, acc[2 * t]);
            acc[2 * t + 1] = fmaf(w, f.y, acc[2 * t + 1]);
        }
    }

    #pragma unroll
    for (int t = 0; t < 8; t++) {
        acc[t] += __shfl_down_sync(0xffffffffu, acc[t], 16);
        acc[t] += __shfl_down_sync(0xffffffffu, acc[t], 8);
    }

    if (q == 0) {
        float d  = g_dis[node];
        float d2 = d * d;
        uint4 sv = hb[(size_t)node * 8 + l8];
        const __half2* sp = (const __half2*)&sv;
        float* ap = g_agg + (size_t)node * 64 + l8 * 8;
        const float* bp = b + l8 * 8;
        float o[8];
        #pragma unroll
        for (int t = 0; t < 4; t++) {
            float2 f = __half22float2(sp[t]);
            o[2 * t]     = fmaf(d2, f.x, acc[2 * t])     + bp[2 * t];
            o[2 * t + 1] = fmaf(d2, f.y, acc[2 * t + 1]) + bp[2 * t + 1];
        }
        *(float4*)(ap)     = make_float4(o[0], o[1], o[2], o[3]);
        *(float4*)(ap + 4) = make_float4(o[4], o[5], o[6], o[7]);
    }
}

// NF=32: 4-lane groups (4 x uint4 = 64B fp16 row) per edge, 8 streams/warp;
// writes final result (neighbors + self + bias) straight to d_out.
__global__ void __launch_bounds__(256)
gather32_kernel(const float* __restrict__ b, float* __restrict__ out) {
    int node = (blockIdx.x * blockDim.x + threadIdx.x) >> 5;
    if (node >= N_NODES) return;
    int lane = threadIdx.x & 31;
    int g  = lane >> 2;           // edge stream 0..7
    int l4 = lane & 3;            // 16B chunk within 64B row

    int start = g_rowstart[node];
    int end   = g_rowstart[node + 1];

    float acc[8];
    #pragma unroll
    for (int t = 0; t < 8; t++) acc[t] = 0.0f;
    const uint4* hb = (const uint4*)g_h;   // 4 uint4 per 32-col row

    for (int k = start + g; k < end; k += 8) {
        int2 e = g_csr[k];
        float w = __int_as_float(e.y);
        uint4 v = hb[(size_t)e.x * 4 + l4];
        const __half2* hp = (const __half2*)&v;
        #pragma unroll
        for (int t = 0; t < 4; t++) {
            float2 f = __half22float2(hp[t]);
            acc[2 * t]     = fmaf(w, f.x, acc[2 * t]);
            acc[2 * t + 1] = fmaf(w, f.y, acc[2 * t + 1]);
        }
    }

    #pragma unroll
    for (int t = 0; t < 8; t++) {
        acc[t] += __shfl_down_sync(0xffffffffu, acc[t], 16);
        acc[t] += __shfl_down_sync(0xffffffffu, acc[t], 8);
        acc[t] += __shfl_down_sync(0xffffffffu, acc[t], 4);
    }

    if (g == 0) {
        float d  = g_dis[node];
        float d2 = d * d;
        uint4 sv = hb[(size_t)node * 4 + l4];
        const __half2* sp = (const __half2*)&sv;
        float* ap = out + (size_t)node * 32 + l4 * 8;
        const float* bp = b + l4 * 8;
        float o[8];
        #pragma unroll
        for (int t = 0; t < 4; t++) {
            float2 f = __half22float2(sp[t]);
            o[2 * t]     = fmaf(d2, f.x, acc[2 * t])     + bp[2 * t];
            o[2 * t + 1] = fmaf(d2, f.y, acc[2 * t + 1]) + bp[2 * t + 1];
        }
        *(float4*)(ap)     = make_float4(o[0], o[1], o[2], o[3]);
        *(float4*)(ap + 4) = make_float4(o[4], o[5], o[6], o[7]);
    }
}

// ---------------- launch -----------------------------------------------------
extern "C" void kernel_launch(void* const* d_in, const int* in_sizes, int n_in,
                              void* d_out, int out_size) {
    const float* x    = (const float*)d_in[0];
    const int*   ei32 = (const int*)d_in[1];   // int32 OR int64 (auto-detected)
    const float* W1 = (const float*)d_in[2];
    const float* b1 = (const float*)d_in[3];
    const float* W2 = (const float*)d_in[4];
    const float* b2 = (const float*)d_in[5];
    const float* W3 = (const float*)d_in[6];
    const float* b3 = (const float*)d_in[7];
    float* out = (float*)d_out;

    const int TPB = 256;
    const int eb  = (N_EDGES + TPB - 1) / TPB;
    const int gemm_blocks   = (N_NODES + 127) / 128;
    const int gather_blocks = (N_NODES * 32 + TPB - 1) / TPB;  // 1 warp/node

    // launch 0: gemm1 (h = x@W1) + dtype detect
    gemm_kernel<64, false, true, true><<<gemm_blocks, 128>>>(x, W1, ei32);
    // CSR build (g_cnt zero-on-entry invariant kept by scan1)
    hist_kernel<<<eb, TPB>>>(ei32);
    scan1_kernel<<<SCAN_NB, 1024>>>();
    scan23_kernel<<<SCAN_NB, 1024>>>();
    fill_kernel<<<eb, TPB>>>(ei32);
    // layer 1 gather
    gather64_kernel<<<gather_blocks, TPB>>>(b1);
    // layer 2
    gemm_kernel<64, true, false, false><<<gemm_blocks, 128>>>(nullptr, W2, ei32);
    gather64_kernel<<<gather_blocks, TPB>>>(b2);
    // layer 3
    gemm_kernel<32, true, false, false><<<gemm_blocks, 128>>>(nullptr, W3, ei32);
    gather32_kernel<<<gather_blocks, TPB>>>(b3, out);
}

// round 8
// speedup vs baseline: 1.8248x; 1.2647x over previous
#include <cuda_runtime.h>
#include <cuda_fp16.h>
#include <math.h>

#define N_NODES 100000
#define N_EDGES 1600000
#define SCAN_NB ((N_NODES + 1023) / 1024)   // 98 blocks

// ---------------- scratch (device globals: no allocation allowed) ----------
__device__ __align__(16) __half g_h[N_NODES * 64];   // h = act(in)@W, fp16
__device__ __align__(16) float  g_agg[N_NODES * 64]; // aggregation (fp32)
__device__ float g_dis[N_NODES];              // rsqrt(deg+1)
__device__ int   g_cnt[N_NODES];              // in-degree; re-zeroed by scan1
__device__ int   g_rowstart[N_NODES + 1];     // CSR row offsets
__device__ int   g_fill[N_NODES];             // atomic fill cursors
__device__ int   g_blocksum[SCAN_NB];
__device__ __align__(16) int2 g_csr[N_EDGES]; // (src, bits(w)) sorted by dst
__device__ int   g_is64;                      // edge_index dtype flag

// ---------------- helpers ---------------------------------------------------
__device__ __forceinline__ unsigned load_idx(const int* ei32, long long pos, int is64) {
    unsigned v = is64 ? (unsigned)ei32[2 * pos] : (unsigned)ei32[pos];
    return (v >= N_NODES) ? 0u : v;   // defensive clamp
}

__device__ __forceinline__ unsigned smem_u32(const void* p) {
    return (unsigned)__cvta_generic_to_shared(p);
}

// ---------------- tensor-core GEMM: g_h = fp16( act(in) @ W ) ---------------
// 256 threads (8 warps), 128 nodes/block; warp w owns M-strip [w*16, w*16+16).
// A (act(in), fp16) via ldmatrix.x4; B (W, fp16) via ldmatrix.x2.trans;
// mma.sync m16n8k16, fp32 accumulate. DETECT: block 0 sniffs edge dtype.
template <int NOUT, bool RELU_IN, bool IN_EXT, bool DETECT>
__global__ void __launch_bounds__(256)
gemm_kernel(const float* __restrict__ ext_in, const float* __restrict__ W,
            const int* __restrict__ ei32) {
    constexpr int AS_STR = 72;            // halves; 144B row stride (bank-safe)
    constexpr int WS_STR = (NOUT == 64) ? 72 : 40;
    constexpr int NT = NOUT / 8;          // 8 or 4 n-tiles per warp strip
    __shared__ __half As[128 * AS_STR];
    __shared__ __half Ws[64 * WS_STR];

    const int tid  = threadIdx.x;
    const int base = blockIdx.x * 128;
    const float* in = IN_EXT ? ext_in : g_agg;

    if (DETECT && blockIdx.x == 0 && tid == 0) {
        int allzero = 1;
        #pragma unroll
        for (int j = 1; j < 128; j += 2) allzero &= (ei32[j] == 0);
        g_is64 = allzero;
    }

    // W: fp32 [64][NOUT] -> fp16 smem [64][WS_STR]
    #pragma unroll 4
    for (int idx = tid; idx < 64 * NOUT / 2; idx += 256) {
        int row = idx / (NOUT / 2), c2 = idx % (NOUT / 2);
        float2 wv = ((const float2*)W)[idx];
        *(half2*)&Ws[row * WS_STR + c2 * 2] = __floats2half2_rn(wv.x, wv.y);
    }

    // A: fp32 [128][64] -> act -> fp16 smem [128][AS_STR]
    // thread t: node = t/2, col half = (t%2)*32 ; 8 float4 loads
    {
        int node = tid >> 1;
        int c0 = (tid & 1) * 32;
        int gnode = base + node;
        __half* dst = &As[node * AS_STR + c0];
        if (gnode < N_NODES) {
            const float4* src = (const float4*)(in + (size_t)gnode * 64 + c0);
            #pragma unroll
            for (int i = 0; i < 8; i++) {
                float4 v = src[i];
                if (RELU_IN) {
                    v.x = fmaxf(v.x, 0.f); v.y = fmaxf(v.y, 0.f);
                    v.z = fmaxf(v.z, 0.f); v.w = fmaxf(v.w, 0.f);
                }
                half2 h0 = __floats2half2_rn(v.x, v.y);
                half2 h1 = __floats2half2_rn(v.z, v.w);
                *(half2*)(dst + i * 4)     = h0;
                *(half2*)(dst + i * 4 + 2) = h1;
            }
        } else {
            #pragma unroll
            for (int i = 0; i < 8; i++) {
                *(half2*)(dst + i * 4)     = __floats2half2_rn(0.f, 0.f);
                *(half2*)(dst + i * 4 + 2) = __floats2half2_rn(0.f, 0.f);
            }
        }
    }
    __syncthreads();

    const int warp = tid >> 5;
    const int lane = tid & 31;
    const int m0 = warp * 16;

    float acc[NT][4];
    #pragma unroll
    for (int n = 0; n < NT; n++)
        #pragma unroll
        for (int i = 0; i < 4; i++) acc[n][i] = 0.0f;

    const unsigned a_base = smem_u32(As);
    const unsigned w_base = smem_u32(Ws);

    #pragma unroll
    for (int ks = 0; ks < 4; ks++) {
        unsigned a0, a1, a2, a3;
        unsigned a_addr = a_base +
            (((m0 + (lane & 15)) * AS_STR + ks * 16 + ((lane >> 4) << 3)) << 1);
        asm volatile("ldmatrix.sync.aligned.m8n8.x4.shared.b16 {%0,%1,%2,%3}, [%4];"
                     : "=r"(a0), "=r"(a1), "=r"(a2), "=r"(a3) : "r"(a_addr));
        #pragma unroll
        for (int nt = 0; nt < NT; nt++) {
            unsigned b0, b1;
            unsigned b_addr = w_base +
                (((ks * 16 + (lane & 15)) * WS_STR + nt * 8) << 1);
            asm volatile("ldmatrix.sync.aligned.m8n8.x2.trans.shared.b16 {%0,%1}, [%2];"
                         : "=r"(b0), "=r"(b1) : "r"(b_addr));
            asm volatile(
                "mma.sync.aligned.m16n8k16.row.col.f32.f16.f16.f32 "
                "{%0,%1,%2,%3},{%4,%5,%6,%7},{%8,%9},{%0,%1,%2,%3};"
                : "+f"(acc[nt][0]), "+f"(acc[nt][1]), "+f"(acc[nt][2]), "+f"(acc[nt][3])
                : "r"(a0), "r"(a1), "r"(a2), "r"(a3), "r"(b0), "r"(b1));
        }
    }

    // epilogue: D frag (row = lane>>2 [+8], cols = nt*8 + (lane&3)*2)
    const int row = lane >> 2;
    const int cp  = (lane & 3) * 2;
    int node0 = base + m0 + row;
    int node1 = node0 + 8;
    #pragma unroll
    for (int nt = 0; nt < NT; nt++) {
        if (node0 < N_NODES)
            *(half2*)(g_h + (size_t)node0 * NOUT + nt * 8 + cp) =
                __floats2half2_rn(acc[nt][0], acc[nt][1]);
        if (node1 < N_NODES)
            *(half2*)(g_h + (size_t)node1 * NOUT + nt * 8 + cp) =
                __floats2half2_rn(acc[nt][2], acc[nt][3]);
    }
}

// ---------------- CSR build -------------------------------------------------
__global__ void hist_kernel(const int* __restrict__ ei32) {
    int e = blockIdx.x * blockDim.x + threadIdx.x;
    if (e < N_EDGES) {
        unsigned d = load_idx(ei32, (long long)N_EDGES + e, g_is64);
        atomicAdd(&g_cnt[d], 1);
    }
}

__global__ void __launch_bounds__(1024) scan1_kernel() {
    __shared__ int s[1024];
    int tid = threadIdx.x;
    int i = blockIdx.x * 1024 + tid;
    int v = (i < N_NODES) ? g_cnt[i] : 0;
    s[tid] = v;
    __syncthreads();
    #pragma unroll
    for (int off = 1; off < 1024; off <<= 1) {
        int t = (tid >= off) ? s[tid - off] : 0;
        __syncthreads();
        s[tid] += t;
        __syncthreads();
    }
    if (i < N_NODES) {
        g_rowstart[i] = s[tid] - v;                  // partial exclusive
        g_dis[i] = rsqrtf((float)v + 1.0f);
        g_cnt[i] = 0;                                // restore zero invariant
    }
    if (tid == 1023) g_blocksum[blockIdx.x] = s[1023];
}

__global__ void __launch_bounds__(1024) scan23_kernel() {
    __shared__ int s[128];
    int tid = threadIdx.x;
    if (tid < 128) s[tid] = (tid < (int)blockIdx.x && tid < SCAN_NB) ? g_blocksum[tid] : 0;
    __syncthreads();
    #pragma unroll
    for (int o = 64; o > 0; o >>= 1) {
        if (tid < o) s[tid] += s[tid + o];
        __syncthreads();
    }
    int offset = s[0];
    int i = blockIdx.x * 1024 + tid;
    if (i < N_NODES) {
        int r = g_rowstart[i] + offset;
        g_rowstart[i] = r;
        g_fill[i] = r;
    }
    if (blockIdx.x == 0 && tid == 0) g_rowstart[N_NODES] = N_EDGES;
}

__global__ void fill_kernel(const int* __restrict__ ei32) {
    int e = blockIdx.x * blockDim.x + threadIdx.x;
    if (e < N_EDGES) {
        int is64 = g_is64;
        unsigned sn = load_idx(ei32, e, is64);
        unsigned dn = load_idx(ei32, (long long)N_EDGES + e, is64);
        float w = g_dis[sn] * g_dis[dn];
        int pos = atomicAdd(&g_fill[dn], 1);
        g_csr[pos] = make_int2((int)sn, __float_as_int(w));
    }
}

// ---------------- gather: agg[i] = sum_j w*h[j] + dis^2*h[i] + b -------------
// NF=64: warp/node; quarter-warp (8 lanes x uint4 = 128B fp16 row) per edge.
__global__ void __launch_bounds__(256)
gather64_kernel(const float* __restrict__ b) {
    int node = (blockIdx.x * blockDim.x + threadIdx.x) >> 5;
    if (node >= N_NODES) return;
    int lane = threadIdx.x & 31;
    int q  = lane >> 3;
    int l8 = lane & 7;

    int start = g_rowstart[node];
    int end   = g_rowstart[node + 1];

    float acc[8];
    #pragma unroll
    for (int t = 0; t < 8; t++) acc[t] = 0.0f;
    const uint4* hb = (const uint4*)g_h;

    for (int k = start + q; k < end; k += 4) {
        int2 e = g_csr[k];
        float w = __int_as_float(e.y);
        uint4 v = hb[(size_t)e.x * 8 + l8];
        const __half2* hp = (const __half2*)&v;
        #pragma unroll
        for (int t = 0; t < 4; t++) {
            float2 f = __half22float2(hp[t]);
            acc[2 * t]     = fmaf(w, f.x, acc[2 * t]);
            acc[2 * t + 1] = fmaf(w, f.y, acc[2 * t + 1]);
        }
    }

    #pragma unroll
    for (int t = 0; t < 8; t++) {
        acc[t] += __shfl_down_sync(0xffffffffu, acc[t], 16);
        acc[t] += __shfl_down_sync(0xffffffffu, acc[t], 8);
    }

    if (q == 0) {
        float d  = g_dis[node];
        float d2 = d * d;
        uint4 sv = hb[(size_t)node * 8 + l8];
        const __half2* sp = (const __half2*)&sv;
        float* ap = g_agg + (size_t)node * 64 + l8 * 8;
        const float* bp = b + l8 * 8;
        float o[8];
        #pragma unroll
        for (int t = 0; t < 4; t++) {
            float2 f = __half22float2(sp[t]);
            o[2 * t]     = fmaf(d2, f.x, acc[2 * t])     + bp[2 * t];
            o[2 * t + 1] = fmaf(d2, f.y, acc[2 * t + 1]) + bp[2 * t + 1];
        }
        *(float4*)(ap)     = make_float4(o[0], o[1], o[2], o[3]);
        *(float4*)(ap + 4) = make_float4(o[4], o[5], o[6], o[7]);
    }
}

// NF=32: 4-lane groups per edge, 8 streams/warp; writes final to d_out.
__global__ void __launch_bounds__(256)
gather32_kernel(const float* __restrict__ b, float* __restrict__ out) {
    int node = (blockIdx.x * blockDim.x + threadIdx.x) >> 5;
    if (node >= N_NODES) return;
    int lane = threadIdx.x & 31;
    int g  = lane >> 2;
    int l4 = lane & 3;

    int start = g_rowstart[node];
    int end   = g_rowstart[node + 1];

    float acc[8];
    #pragma unroll
    for (int t = 0; t < 8; t++) acc[t] = 0.0f;
    const uint4* hb = (const uint4*)g_h;

    for (int k = start + g; k < end; k += 8) {
        int2 e = g_csr[k];
        float w = __int_as_float(e.y);
        uint4 v = hb[(size_t)e.x * 4 + l4];
        const __half2* hp = (const __half2*)&v;
        #pragma unroll
        for (int t = 0; t < 4; t++) {
            float2 f = __half22float2(hp[t]);
            acc[2 * t]     = fmaf(w, f.x, acc[2 * t]);
            acc[2 * t + 1] = fmaf(w, f.y, acc[2 * t + 1]);
        }
    }

    #pragma unroll
    for (int t = 0; t < 8; t++) {
        acc[t] += __shfl_down_sync(0xffffffffu, acc[t], 16);
        acc[t] += __shfl_down_sync(0xffffffffu, acc[t], 8);
        acc[t] += __shfl_down_sync(0xffffffffu, acc[t], 4);
    }

    if (g == 0) {
        float d  = g_dis[node];
        float d2 = d * d;
        uint4 sv = hb[(size_t)node * 4 + l4];
        const __half2* sp = (const __half2*)&sv;
        float* ap = out + (size_t)node * 32 + l4 * 8;
        const float* bp = b + l4 * 8;
        float o[8];
        #pragma unroll
        for (int t = 0; t < 4; t++) {
            float2 f = __half22float2(sp[t]);
            o[2 * t]     = fmaf(d2, f.x, acc[2 * t])     + bp[2 * t];
            o[2 * t + 1] = fmaf(d2, f.y, acc[2 * t + 1]) + bp[2 * t + 1];
        }
        *(float4*)(ap)     = make_float4(o[0], o[1], o[2], o[3]);
        *(float4*)(ap + 4) = make_float4(o[4], o[5], o[6], o[7]);
    }
}

// ---------------- launch -----------------------------------------------------
extern "C" void kernel_launch(void* const* d_in, const int* in_sizes, int n_in,
                              void* d_out, int out_size) {
    const float* x    = (const float*)d_in[0];
    const int*   ei32 = (const int*)d_in[1];   // int32 OR int64 (auto-detected)
    const float* W1 = (const float*)d_in[2];
    const float* b1 = (const float*)d_in[3];
    const float* W2 = (const float*)d_in[4];
    const float* b2 = (const float*)d_in[5];
    const float* W3 = (const float*)d_in[6];
    const float* b3 = (const float*)d_in[7];
    float* out = (float*)d_out;

    const int TPB = 256;
    const int eb  = (N_EDGES + TPB - 1) / TPB;
    const int gemm_blocks   = (N_NODES + 127) / 128;
    const int gather_blocks = (N_NODES * 32 + TPB - 1) / TPB;  // 1 warp/node

    // launch 0: gemm1 (h = x@W1, tensor cores) + dtype detect
    gemm_kernel<64, false, true, true><<<gemm_blocks, TPB>>>(x, W1, ei32);
    // CSR build (g_cnt zero-on-entry invariant kept by scan1)
    hist_kernel<<<eb, TPB>>>(ei32);
    scan1_kernel<<<SCAN_NB, 1024>>>();
    scan23_kernel<<<SCAN_NB, 1024>>>();
    fill_kernel<<<eb, TPB>>>(ei32);
    // layer 1 gather
    gather64_kernel<<<gather_blocks, TPB>>>(b1);
    // layer 2
    gemm_kernel<64, true, false, false><<<gemm_blocks, TPB>>>(nullptr, W2, ei32);
    gather64_kernel<<<gather_blocks, TPB>>>(b2);
    // layer 3
    gemm_kernel<32, true, false, false><<<gemm_blocks, TPB>>>(nullptr, W3, ei32);
    gather32_kernel<<<gather_blocks, TPB>>>(b3, out);
}

// round 10
// speedup vs baseline: 1.8267x; 1.0010x over previous
#include <cuda_runtime.h>
#include <cuda_fp16.h>
#include <math.h>

#define N_NODES 100000
#define N_EDGES 1600000
#define SCAN_NB ((N_NODES + 1023) / 1024)       // 98 blocks
#define GEMM_BLOCKS ((N_NODES + 127) / 128)     // 782
#define HIST_BLOCKS ((N_EDGES + 255) / 256)     // 6250

// ---------------- scratch (device globals: no allocation allowed) ----------
__device__ __align__(16) __half g_h[N_NODES * 64];   // h = act(in)@W, fp16
__device__ __align__(16) float  g_agg[N_NODES * 64]; // aggregation (fp32)
__device__ float g_dis[N_NODES];               // rsqrt(deg+1)
__device__ int   g_cnt[N_NODES];               // in-degree; re-zeroed by scan
__device__ int   g_rowstart[N_NODES + 1];      // CSR row offsets
__device__ int   g_fill[N_NODES];              // atomic fill cursors
__device__ unsigned long long g_desc[SCAN_NB]; // lookback descriptors
__device__ __align__(16) int2 g_csr[N_EDGES];  // (src, bits(w)) sorted by dst

// ---------------- helpers ---------------------------------------------------
__device__ __forceinline__ unsigned load_idx(const int* ei32, long long pos, int is64) {
    unsigned v = is64 ? (unsigned)ei32[2 * pos] : (unsigned)ei32[pos];
    return (v >= N_NODES) ? 0u : v;   // defensive clamp
}

// per-block edge dtype sniff: JAX int64 LE with ids < 2^17 -> odd words all 0
__device__ __forceinline__ int detect_is64_block(const int* ei32, int* s64, int tid) {
    if (tid == 0) {
        int az = 1;
        #pragma unroll
        for (int j = 1; j < 128; j += 2) az &= (ei32[j] == 0);
        *s64 = az;
    }
    __syncthreads();
    return *s64;
}

__device__ __forceinline__ unsigned smem_u32(const void* p) {
    return (unsigned)__cvta_generic_to_shared(p);
}

// ---------------- tensor-core GEMM body: g_h = fp16( act(in) @ W ) ----------
// 256 threads, 128 nodes/block; mma.sync m16n8k16, fp32 accumulate.
// NOTE: smem tiles MUST be 16B-aligned for ldmatrix (R9 failed on this).
template <int NOUT, bool RELU_IN, bool IN_EXT>
__device__ __forceinline__ void gemm_body(const float* __restrict__ ext_in,
                                          const float* __restrict__ W,
                                          int bidx, int tid) {
    constexpr int AS_STR = 72;            // halves; 144B = 9*16B row stride
    constexpr int WS_STR = (NOUT == 64) ? 72 : 40;  // 144B / 80B, both 16B-mult
    constexpr int NT = NOUT / 8;
    __shared__ __align__(16) __half As[128 * AS_STR];
    __shared__ __align__(16) __half Ws[64 * WS_STR];

    const int base = bidx * 128;
    const float* in = IN_EXT ? ext_in : g_agg;

    #pragma unroll 4
    for (int idx = tid; idx < 64 * NOUT / 2; idx += 256) {
        int row = idx / (NOUT / 2), c2 = idx % (NOUT / 2);
        float2 wv = ((const float2*)W)[idx];
        *(half2*)&Ws[row * WS_STR + c2 * 2] = __floats2half2_rn(wv.x, wv.y);
    }

    {
        int node = tid >> 1;
        int c0 = (tid & 1) * 32;
        int gnode = base + node;
        __half* dst = &As[node * AS_STR + c0];
        if (gnode < N_NODES) {
            const float4* src = (const float4*)(in + (size_t)gnode * 64 + c0);
            #pragma unroll
            for (int i = 0; i < 8; i++) {
                float4 v = src[i];
                if (RELU_IN) {
                    v.x = fmaxf(v.x, 0.f); v.y = fmaxf(v.y, 0.f);
                    v.z = fmaxf(v.z, 0.f); v.w = fmaxf(v.w, 0.f);
                }
                *(half2*)(dst + i * 4)     = __floats2half2_rn(v.x, v.y);
                *(half2*)(dst + i * 4 + 2) = __floats2half2_rn(v.z, v.w);
            }
        } else {
            #pragma unroll
            for (int i = 0; i < 8; i++) {
                *(half2*)(dst + i * 4)     = __floats2half2_rn(0.f, 0.f);
                *(half2*)(dst + i * 4 + 2) = __floats2half2_rn(0.f, 0.f);
            }
        }
    }
    __syncthreads();

    const int warp = tid >> 5;
    const int lane = tid & 31;
    const int m0 = warp * 16;

    float acc[NT][4];
    #pragma unroll
    for (int n = 0; n < NT; n++)
        #pragma unroll
        for (int i = 0; i < 4; i++) acc[n][i] = 0.0f;

    const unsigned a_base = smem_u32(As);
    const unsigned w_base = smem_u32(Ws);

    #pragma unroll
    for (int ks = 0; ks < 4; ks++) {
        unsigned a0, a1, a2, a3;
        unsigned a_addr = a_base +
            (((m0 + (lane & 15)) * AS_STR + ks * 16 + ((lane >> 4) << 3)) << 1);
        asm volatile("ldmatrix.sync.aligned.m8n8.x4.shared.b16 {%0,%1,%2,%3}, [%4];"
                     : "=r"(a0), "=r"(a1), "=r"(a2), "=r"(a3) : "r"(a_addr));
        #pragma unroll
        for (int nt = 0; nt < NT; nt++) {
            unsigned b0, b1;
            unsigned b_addr = w_base +
                (((ks * 16 + (lane & 15)) * WS_STR + nt * 8) << 1);
            asm volatile("ldmatrix.sync.aligned.m8n8.x2.trans.shared.b16 {%0,%1}, [%2];"
                         : "=r"(b0), "=r"(b1) : "r"(b_addr));
            asm volatile(
                "mma.sync.aligned.m16n8k16.row.col.f32.f16.f16.f32 "
                "{%0,%1,%2,%3},{%4,%5,%6,%7},{%8,%9},{%0,%1,%2,%3};"
                : "+f"(acc[nt][0]), "+f"(acc[nt][1]), "+f"(acc[nt][2]), "+f"(acc[nt][3])
                : "r"(a0), "r"(a1), "r"(a2), "r"(a3), "r"(b0), "r"(b1));
        }
    }

    const int row = lane >> 2;
    const int cp  = (lane & 3) * 2;
    int node0 = base + m0 + row;
    int node1 = node0 + 8;
    #pragma unroll
    for (int nt = 0; nt < NT; nt++) {
        if (node0 < N_NODES)
            *(half2*)(g_h + (size_t)node0 * NOUT + nt * 8 + cp) =
                __floats2half2_rn(acc[nt][0], acc[nt][1]);
        if (node1 < N_NODES)
            *(half2*)(g_h + (size_t)node1 * NOUT + nt * 8 + cp) =
                __floats2half2_rn(acc[nt][2], acc[nt][3]);
    }
}

// ---------------- launch 0: fused gemm1 + hist + desc reset -----------------
__global__ void __launch_bounds__(256)
fused_gemm1_hist_kernel(const float* __restrict__ x, const float* __restrict__ W1,
                        const int* __restrict__ ei32) {
    __shared__ int s64;
    int tid = threadIdx.x;
    if (blockIdx.x < GEMM_BLOCKS) {
        gemm_body<64, false, true>(x, W1, blockIdx.x, tid);
    } else {
        int hb = blockIdx.x - GEMM_BLOCKS;
        if (hb == 0 && tid < SCAN_NB) g_desc[tid] = 0ULL;   // reset lookback
        int is64 = detect_is64_block(ei32, &s64, tid);
        int e = hb * 256 + tid;
        if (e < N_EDGES) {
            unsigned d = load_idx(ei32, (long long)N_EDGES + e, is64);
            atomicAdd(&g_cnt[d], 1);
        }
    }
}

// ---------------- launch 1: single-pass scan (decoupled lookback) -----------
// Also writes dis, fill-init, re-zeros cnt, sets rowstart[N_NODES].
__global__ void __launch_bounds__(1024) scan_kernel() {
    __shared__ int s_warp[32];
    __shared__ int s_prefix;
    const unsigned FULL = 0xffffffffu;
    int tid = threadIdx.x, lane = tid & 31, wid = tid >> 5;
    int bid = blockIdx.x;
    int i = bid * 1024 + tid;
    int v = (i < N_NODES) ? g_cnt[i] : 0;

    // warp-inclusive scan
    int s = v;
    #pragma unroll
    for (int o = 1; o < 32; o <<= 1) {
        int t = __shfl_up_sync(FULL, s, o);
        if (lane >= o) s += t;
    }
    if (lane == 31) s_warp[wid] = s;
    __syncthreads();
    if (wid == 0) {
        int ws = s_warp[lane];
        #pragma unroll
        for (int o = 1; o < 32; o <<= 1) {
            int t = __shfl_up_sync(FULL, ws, o);
            if (lane >= o) ws += t;
        }
        s_warp[lane] = ws;
    }
    __syncthreads();
    int warp_excl = (wid == 0) ? 0 : s_warp[wid - 1];
    int incl  = s + warp_excl;            // block-inclusive scan value
    int total = s_warp[31];

    // publish + warp-parallel lookback (warp 0)
    if (wid == 0) {
        if (lane == 0) {
            unsigned long long d =
                ((unsigned long long)((bid == 0) ? 2 : 1) << 32) | (unsigned)total;
            atomicExch(&g_desc[bid], d);
        }
        int prefix = 0;
        if (bid > 0) {
            int j = bid - 1;
            while (j >= 0) {
                int idx = j - lane;
                bool valid = idx >= 0;
                unsigned long long d = 0;
                bool done;
                do {
                    if (valid) d = *((volatile unsigned long long*)&g_desc[idx]);
                    done = !valid || (d >> 32) != 0;
                } while (!__all_sync(FULL, done));
                unsigned pm = __ballot_sync(FULL, valid && (d >> 32) == 2);
                int contrib;
                if (pm) {
                    int fp = __ffs(pm) - 1;
                    contrib = (valid && lane <= fp) ? (int)(unsigned)d : 0;
                } else {
                    contrib = valid ? (int)(unsigned)d : 0;
                }
                #pragma unroll
                for (int o = 16; o > 0; o >>= 1)
                    contrib += __shfl_down_sync(FULL, contrib, o);
                if (lane == 0) prefix += contrib;
                if (pm) break;
                j -= 32;
            }
            if (lane == 0)
                atomicExch(&g_desc[bid], (2ULL << 32) | (unsigned)(prefix + total));
        }
        if (lane == 0) s_prefix = prefix;
    }
    __syncthreads();

    int pr = s_prefix;
    if (i < N_NODES) {
        int excl = pr + incl - v;
        g_rowstart[i] = excl;
        g_fill[i]     = excl;
        g_dis[i]      = rsqrtf((float)v + 1.0f);
        g_cnt[i]      = 0;                       // zero-on-entry invariant
    }
    if (bid == 0 && tid == 0) g_rowstart[N_NODES] = N_EDGES;
}

// ---------------- launch 2: fill CSR ----------------------------------------
__global__ void __launch_bounds__(256) fill_kernel(const int* __restrict__ ei32) {
    __shared__ int s64;
    int tid = threadIdx.x;
    int is64 = detect_is64_block(ei32, &s64, tid);
    int e = blockIdx.x * 256 + tid;
    if (e < N_EDGES) {
        unsigned sn = load_idx(ei32, e, is64);
        unsigned dn = load_idx(ei32, (long long)N_EDGES + e, is64);
        float w = g_dis[sn] * g_dis[dn];
        int pos = atomicAdd(&g_fill[dn], 1);
        g_csr[pos] = make_int2((int)sn, __float_as_int(w));
    }
}

// ---------------- gather: agg[i] = sum_j w*h[j] + dis^2*h[i] + b -------------
// NF=64: warp/node; 32 CSR entries staged per coalesced warp load + shfl
// broadcast; quarter-warp (8 lanes x uint4 = 128B fp16 row) per edge; unroll 2.
__global__ void __launch_bounds__(256)
gather64_kernel(const float* __restrict__ b) {
    const unsigned FULL = 0xffffffffu;
    int node = (blockIdx.x * blockDim.x + threadIdx.x) >> 5;
    if (node >= N_NODES) return;
    int lane = threadIdx.x & 31;
    int q  = lane >> 3;
    int l8 = lane & 7;

    int start = g_rowstart[node];
    int n     = g_rowstart[node + 1] - start;

    float acc[8];
    #pragma unroll
    for (int t = 0; t < 8; t++) acc[t] = 0.0f;
    const uint4* hb = (const uint4*)g_h;

    for (int kb = 0; kb < n; kb += 32) {
        int lim = n - kb; if (lim > 32) lim = 32;
        int2 me = make_int2(0, 0);
        if (lane < lim) me = g_csr[start + kb + lane];
        #pragma unroll 2
        for (int t0 = 0; t0 < lim; t0 += 4) {
            int t = t0 + q;
            int sl = (t < 32) ? t : 31;
            int src = __shfl_sync(FULL, me.x, sl);
            int wb  = __shfl_sync(FULL, me.y, sl);
            if (t < lim) {
                float w = __int_as_float(wb);
                uint4 v = hb[(size_t)src * 8 + l8];
                const __half2* hp = (const __half2*)&v;
                #pragma unroll
                for (int u = 0; u < 4; u++) {
                    float2 f = __half22float2(hp[u]);
                    acc[2 * u]     = fmaf(w, f.x, acc[2 * u]);
                    acc[2 * u + 1] = fmaf(w, f.y, acc[2 * u + 1]);
                }
            }
        }
    }

    #pragma unroll
    for (int t = 0; t < 8; t++) {
        acc[t] += __shfl_down_sync(FULL, acc[t], 16);
        acc[t] += __shfl_down_sync(FULL, acc[t], 8);
    }

    if (q == 0) {
        float d  = g_dis[node];
        float d2 = d * d;
        uint4 sv = hb[(size_t)node * 8 + l8];
        const __half2* sp = (const __half2*)&sv;
        float* ap = g_agg + (size_t)node * 64 + l8 * 8;
        const float* bp = b + l8 * 8;
        float o[8];
        #pragma unroll
        for (int u = 0; u < 4; u++) {
            float2 f = __half22float2(sp[u]);
            o[2 * u]     = fmaf(d2, f.x, acc[2 * u])     + bp[2 * u];
            o[2 * u + 1] = fmaf(d2, f.y, acc[2 * u + 1]) + bp[2 * u + 1];
        }
        *(float4*)(ap)     = make_float4(o[0], o[1], o[2], o[3]);
        *(float4*)(ap + 4) = make_float4(o[4], o[5], o[6], o[7]);
    }
}

// NF=32: 4-lane groups (uint4 = 64B row), 8 edge slots/warp; final to d_out.
__global__ void __launch_bounds__(256)
gather32_kernel(const float* __restrict__ b, float* __restrict__ out) {
    const unsigned FULL = 0xffffffffu;
    int node = (blockIdx.x * blockDim.x + threadIdx.x) >> 5;
    if (node >= N_NODES) return;
    int lane = threadIdx.x & 31;
    int g  = lane >> 2;
    int l4 = lane & 3;

    int start = g_rowstart[node];
    int n     = g_rowstart[node + 1] - start;

    float acc[8];
    #pragma unroll
    for (int t = 0; t < 8; t++) acc[t] = 0.0f;
    const uint4* hb = (const uint4*)g_h;

    for (int kb = 0; kb < n; kb += 32) {
        int lim = n - kb; if (lim > 32) lim = 32;
        int2 me = make_int2(0, 0);
        if (lane < lim) me = g_csr[start + kb + lane];
        #pragma unroll 2
        for (int t0 = 0; t0 < lim; t0 += 8) {
            int t = t0 + g;
            int sl = (t < 32) ? t : 31;
            int src = __shfl_sync(FULL, me.x, sl);
            int wb  = __shfl_sync(FULL, me.y, sl);
            if (t < lim) {
                float w = __int_as_float(wb);
                uint4 v = hb[(size_t)src * 4 + l4];
                const __half2* hp = (const __half2*)&v;
                #pragma unroll
                for (int u = 0; u < 4; u++) {
                    float2 f = __half22float2(hp[u]);
                    acc[2 * u]     = fmaf(w, f.x, acc[2 * u]);
                    acc[2 * u + 1] = fmaf(w, f.y, acc[2 * u + 1]);
                }
            }
        }
    }

    #pragma unroll
    for (int t = 0; t < 8; t++) {
        acc[t] += __shfl_down_sync(FULL, acc[t], 16);
        acc[t] += __shfl_down_sync(FULL, acc[t], 8);
        acc[t] += __shfl_down_sync(FULL, acc[t], 4);
    }

    if (g == 0) {
        float d  = g_dis[node];
        float d2 = d * d;
        uint4 sv = hb[(size_t)node * 4 + l4];
        const __half2* sp = (const __half2*)&sv;
        float* ap = out + (size_t)node * 32 + l4 * 8;
        const float* bp = b + l4 * 8;
        float o[8];
        #pragma unroll
        for (int u = 0; u < 4; u++) {
            float2 f = __half22float2(sp[u]);
            o[2 * u]     = fmaf(d2, f.x, acc[2 * u])     + bp[2 * u];
            o[2 * u + 1] = fmaf(d2, f.y, acc[2 * u + 1]) + bp[2 * u + 1];
        }
        *(float4*)(ap)     = make_float4(o[0], o[1], o[2], o[3]);
        *(float4*)(ap + 4) = make_float4(o[4], o[5], o[6], o[7]);
    }
}

// ---------------- plain GEMM kernels (layers 2,3) ---------------------------
template <int NOUT>
__global__ void __launch_bounds__(256)
gemm_kernel(const float* __restrict__ W) {
    gemm_body<NOUT, true, false>(nullptr, W, blockIdx.x, threadIdx.x);
}

// ---------------- launch -----------------------------------------------------
extern "C" void kernel_launch(void* const* d_in, const int* in_sizes, int n_in,
                              void* d_out, int out_size) {
    const float* x    = (const float*)d_in[0];
    const int*   ei32 = (const int*)d_in[1];   // int32 OR int64 (auto-detected)
    const float* W1 = (const float*)d_in[2];
    const float* b1 = (const float*)d_in[3];
    const float* W2 = (const float*)d_in[4];
    const float* b2 = (const float*)d_in[5];
    const float* W3 = (const float*)d_in[6];
    const float* b3 = (const float*)d_in[7];
    float* out = (float*)d_out;

    const int TPB = 256;
    const int gather_blocks = (N_NODES * 32 + TPB - 1) / TPB;  // 1 warp/node

    // 0: gemm1 (tensor cores) + degree hist + lookback-desc reset
    fused_gemm1_hist_kernel<<<GEMM_BLOCKS + HIST_BLOCKS, TPB>>>(x, W1, ei32);
    // 1: single-pass scan (rowstart, dis, fill-init, cnt re-zero)
    scan_kernel<<<SCAN_NB, 1024>>>();
    // 2: CSR fill
    fill_kernel<<<HIST_BLOCKS, TPB>>>(ei32);
    // 3: layer-1 gather  (ncu captures launch index 3)
    gather64_kernel<<<gather_blocks, TPB>>>(b1);
    // layer 2
    gemm_kernel<64><<<GEMM_BLOCKS, TPB>>>(W2);
    gather64_kernel<<<gather_blocks, TPB>>>(b2);
    // layer 3
    gemm_kernel<32><<<GEMM_BLOCKS, TPB>>>(W3);
    gather32_kernel<<<gather_blocks, TPB>>>(b3, out);
}

// round 11
// speedup vs baseline: 2.0418x; 1.1178x over previous
#include <cuda_runtime.h>
#include <cuda_fp16.h>
#include <math.h>

#define N_NODES 100000
#define N_EDGES 1600000
#define SCAN_NB ((N_NODES + 1023) / 1024)       // 98 blocks
#define GEMM_BLOCKS ((N_NODES + 127) / 128)     // 782
#define HIST_BLOCKS ((N_EDGES + 255) / 256)     // 6250

// ---------------- scratch (device globals: no allocation allowed) ----------
__device__ __align__(16) __half g_h[N_NODES * 64];   // h = in@W, fp16
__device__ __align__(16) __half g_agg[N_NODES * 64]; // relu(conv) fp16 (L1,L2)
__device__ float g_dis[N_NODES];               // rsqrt(deg+1)
__device__ int   g_cnt[N_NODES];               // in-degree; re-zeroed by scan
__device__ int   g_rowstart[N_NODES + 1];      // CSR row offsets
__device__ int   g_fill[N_NODES];              // atomic fill cursors
__device__ unsigned long long g_desc[SCAN_NB]; // lookback descriptors
__device__ __align__(16) int2 g_csr[N_EDGES];  // (src, bits(w)) sorted by dst

// ---------------- helpers ---------------------------------------------------
__device__ __forceinline__ unsigned load_idx(const int* ei32, long long pos, int is64) {
    unsigned v = is64 ? (unsigned)ei32[2 * pos] : (unsigned)ei32[pos];
    return (v >= N_NODES) ? 0u : v;   // defensive clamp
}

// per-block edge dtype sniff: JAX int64 LE with ids < 2^17 -> odd words all 0
__device__ __forceinline__ int detect_is64_block(const int* ei32, int* s64, int tid) {
    if (tid == 0) {
        int az = 1;
        #pragma unroll
        for (int j = 1; j < 128; j += 2) az &= (ei32[j] == 0);
        *s64 = az;
    }
    __syncthreads();
    return *s64;
}

__device__ __forceinline__ unsigned smem_u32(const void* p) {
    return (unsigned)__cvta_generic_to_shared(p);
}

// ---------------- tensor-core GEMM body: g_h = fp16( in @ W ) ---------------
// 256 threads, 128 nodes/block; mma.sync m16n8k16, fp32 accumulate.
// IN_EXT: fp32 input (x). else: fp16 input (g_agg, relu already applied).
// smem tiles 16B-aligned (ldmatrix requirement).
template <int NOUT, bool IN_EXT>
__device__ __forceinline__ void gemm_body(const float* __restrict__ ext_in,
                                          const float* __restrict__ W,
                                          int bidx, int tid) {
    constexpr int AS_STR = 72;            // halves; 144B = 9*16B row stride
    constexpr int WS_STR = (NOUT == 64) ? 72 : 40;
    constexpr int NT = NOUT / 8;
    __shared__ __align__(16) __half As[128 * AS_STR];
    __shared__ __align__(16) __half Ws[64 * WS_STR];

    const int base = bidx * 128;

    #pragma unroll 4
    for (int idx = tid; idx < 64 * NOUT / 2; idx += 256) {
        int row = idx / (NOUT / 2), c2 = idx % (NOUT / 2);
        float2 wv = ((const float2*)W)[idx];
        *(half2*)&Ws[row * WS_STR + c2 * 2] = __floats2half2_rn(wv.x, wv.y);
    }

    {
        int node = tid >> 1;
        int c0 = (tid & 1) * 32;
        int gnode = base + node;
        __half* dst = &As[node * AS_STR + c0];
        if (gnode < N_NODES) {
            if (IN_EXT) {
                const float4* src = (const float4*)(ext_in + (size_t)gnode * 64 + c0);
                #pragma unroll
                for (int i = 0; i < 8; i++) {
                    float4 v = src[i];
                    *(half2*)(dst + i * 4)     = __floats2half2_rn(v.x, v.y);
                    *(half2*)(dst + i * 4 + 2) = __floats2half2_rn(v.z, v.w);
                }
            } else {
                const uint4* src = (const uint4*)(g_agg + (size_t)gnode * 64 + c0);
                #pragma unroll
                for (int i = 0; i < 4; i++)
                    ((uint4*)dst)[i] = src[i];
            }
        } else {
            #pragma unroll
            for (int i = 0; i < 4; i++)
                ((uint4*)dst)[i] = make_uint4(0, 0, 0, 0);
        }
    }
    __syncthreads();

    const int warp = tid >> 5;
    const int lane = tid & 31;
    const int m0 = warp * 16;

    float acc[NT][4];
    #pragma unroll
    for (int n = 0; n < NT; n++)
        #pragma unroll
        for (int i = 0; i < 4; i++) acc[n][i] = 0.0f;

    const unsigned a_base = smem_u32(As);
    const unsigned w_base = smem_u32(Ws);

    #pragma unroll
    for (int ks = 0; ks < 4; ks++) {
        unsigned a0, a1, a2, a3;
        unsigned a_addr = a_base +
            (((m0 + (lane & 15)) * AS_STR + ks * 16 + ((lane >> 4) << 3)) << 1);
        asm volatile("ldmatrix.sync.aligned.m8n8.x4.shared.b16 {%0,%1,%2,%3}, [%4];"
                     : "=r"(a0), "=r"(a1), "=r"(a2), "=r"(a3) : "r"(a_addr));
        #pragma unroll
        for (int nt = 0; nt < NT; nt++) {
            unsigned b0, b1;
            unsigned b_addr = w_base +
                (((ks * 16 + (lane & 15)) * WS_STR + nt * 8) << 1);
            asm volatile("ldmatrix.sync.aligned.m8n8.x2.trans.shared.b16 {%0,%1}, [%2];"
                         : "=r"(b0), "=r"(b1) : "r"(b_addr));
            asm volatile(
                "mma.sync.aligned.m16n8k16.row.col.f32.f16.f16.f32 "
                "{%0,%1,%2,%3},{%4,%5,%6,%7},{%8,%9},{%0,%1,%2,%3};"
                : "+f"(acc[nt][0]), "+f"(acc[nt][1]), "+f"(acc[nt][2]), "+f"(acc[nt][3])
                : "r"(a0), "r"(a1), "r"(a2), "r"(a3), "r"(b0), "r"(b1));
        }
    }

    const int row = lane >> 2;
    const int cp  = (lane & 3) * 2;
    int node0 = base + m0 + row;
    int node1 = node0 + 8;
    #pragma unroll
    for (int nt = 0; nt < NT; nt++) {
        if (node0 < N_NODES)
            *(half2*)(g_h + (size_t)node0 * NOUT + nt * 8 + cp) =
                __floats2half2_rn(acc[nt][0], acc[nt][1]);
        if (node1 < N_NODES)
            *(half2*)(g_h + (size_t)node1 * NOUT + nt * 8 + cp) =
                __floats2half2_rn(acc[nt][2], acc[nt][3]);
    }
}

// ---------------- launch 0: fused gemm1 + hist + desc reset -----------------
__global__ void __launch_bounds__(256)
fused_gemm1_hist_kernel(const float* __restrict__ x, const float* __restrict__ W1,
                        const int* __restrict__ ei32) {
    __shared__ int s64;
    int tid = threadIdx.x;
    if (blockIdx.x < GEMM_BLOCKS) {
        gemm_body<64, true>(x, W1, blockIdx.x, tid);
    } else {
        int hb = blockIdx.x - GEMM_BLOCKS;
        if (hb == 0 && tid < SCAN_NB) g_desc[tid] = 0ULL;   // reset lookback
        int is64 = detect_is64_block(ei32, &s64, tid);
        int e = hb * 256 + tid;
        if (e < N_EDGES) {
            unsigned d = load_idx(ei32, (long long)N_EDGES + e, is64);
            atomicAdd(&g_cnt[d], 1);
        }
    }
}

// ---------------- launch 1: single-pass scan (decoupled lookback) -----------
__global__ void __launch_bounds__(1024) scan_kernel() {
    __shared__ int s_warp[32];
    __shared__ int s_prefix;
    const unsigned FULL = 0xffffffffu;
    int tid = threadIdx.x, lane = tid & 31, wid = tid >> 5;
    int bid = blockIdx.x;
    int i = bid * 1024 + tid;
    int v = (i < N_NODES) ? g_cnt[i] : 0;

    int s = v;
    #pragma unroll
    for (int o = 1; o < 32; o <<= 1) {
        int t = __shfl_up_sync(FULL, s, o);
        if (lane >= o) s += t;
    }
    if (lane == 31) s_warp[wid] = s;
    __syncthreads();
    if (wid == 0) {
        int ws = s_warp[lane];
        #pragma unroll
        for (int o = 1; o < 32; o <<= 1) {
            int t = __shfl_up_sync(FULL, ws, o);
            if (lane >= o) ws += t;
        }
        s_warp[lane] = ws;
    }
    __syncthreads();
    int warp_excl = (wid == 0) ? 0 : s_warp[wid - 1];
    int incl  = s + warp_excl;
    int total = s_warp[31];

    if (wid == 0) {
        if (lane == 0) {
            unsigned long long d =
                ((unsigned long long)((bid == 0) ? 2 : 1) << 32) | (unsigned)total;
            atomicExch(&g_desc[bid], d);
        }
        int prefix = 0;
        if (bid > 0) {
            int j = bid - 1;
            while (j >= 0) {
                int idx = j - lane;
                bool valid = idx >= 0;
                unsigned long long d = 0;
                bool done;
                do {
                    if (valid) d = *((volatile unsigned long long*)&g_desc[idx]);
                    done = !valid || (d >> 32) != 0;
                } while (!__all_sync(FULL, done));
                unsigned pm = __ballot_sync(FULL, valid && (d >> 32) == 2);
                int contrib;
                if (pm) {
                    int fp = __ffs(pm) - 1;
                    contrib = (valid && lane <= fp) ? (int)(unsigned)d : 0;
                } else {
                    contrib = valid ? (int)(unsigned)d : 0;
                }
                #pragma unroll
                for (int o = 16; o > 0; o >>= 1)
                    contrib += __shfl_down_sync(FULL, contrib, o);
                if (lane == 0) prefix += contrib;
                if (pm) break;
                j -= 32;
            }
            if (lane == 0)
                atomicExch(&g_desc[bid], (2ULL << 32) | (unsigned)(prefix + total));
        }
        if (lane == 0) s_prefix = prefix;
    }
    __syncthreads();

    int pr = s_prefix;
    if (i < N_NODES) {
        int excl = pr + incl - v;
        g_rowstart[i] = excl;
        g_fill[i]     = excl;
        g_dis[i]      = rsqrtf((float)v + 1.0f);
        g_cnt[i]      = 0;                       // zero-on-entry invariant
    }
    if (bid == 0 && tid == 0) g_rowstart[N_NODES] = N_EDGES;
}

// ---------------- launch 2: fill CSR ----------------------------------------
__global__ void __launch_bounds__(256) fill_kernel(const int* __restrict__ ei32) {
    __shared__ int s64;
    int tid = threadIdx.x;
    int is64 = detect_is64_block(ei32, &s64, tid);
    int e = blockIdx.x * 256 + tid;
    if (e < N_EDGES) {
        unsigned sn = load_idx(ei32, e, is64);
        unsigned dn = load_idx(ei32, (long long)N_EDGES + e, is64);
        float w = g_dis[sn] * g_dis[dn];
        int pos = atomicAdd(&g_fill[dn], 1);
        g_csr[pos] = make_int2((int)sn, __float_as_int(w));
    }
}

// ---------------- gather64: agg = fp16(relu(sum w*h + dis^2*h + b)) ----------
// Warp/node; quarter-warp (8 lanes x uint4 = 128B fp16 row) per edge stream,
// direct per-group CSR loads, unroll 2 -> up to 8 h-rows in flight per warp.
__global__ void __launch_bounds__(256)
gather64_kernel(const float* __restrict__ b) {
    const unsigned FULL = 0xffffffffu;
    int node = (blockIdx.x * blockDim.x + threadIdx.x) >> 5;
    if (node >= N_NODES) return;
    int lane = threadIdx.x & 31;
    int q  = lane >> 3;
    int l8 = lane & 7;

    int start = g_rowstart[node];
    int end   = g_rowstart[node + 1];

    float acc[8];
    #pragma unroll
    for (int t = 0; t < 8; t++) acc[t] = 0.0f;
    const uint4* hb = (const uint4*)g_h;

    #pragma unroll 2
    for (int k = start + q; k < end; k += 4) {
        int2 e = g_csr[k];
        float w = __int_as_float(e.y);
        uint4 v = hb[(unsigned)e.x * 8u + l8];
        const __half2* hp = (const __half2*)&v;
        #pragma unroll
        for (int u = 0; u < 4; u++) {
            float2 f = __half22float2(hp[u]);
            acc[2 * u]     = fmaf(w, f.x, acc[2 * u]);
            acc[2 * u + 1] = fmaf(w, f.y, acc[2 * u + 1]);
        }
    }

    #pragma unroll
    for (int t = 0; t < 8; t++) {
        acc[t] += __shfl_down_sync(FULL, acc[t], 16);
        acc[t] += __shfl_down_sync(FULL, acc[t], 8);
    }

    if (q == 0) {
        float d  = g_dis[node];
        float d2 = d * d;
        uint4 sv = hb[(unsigned)node * 8u + l8];
        const __half2* sp = (const __half2*)&sv;
        const float* bp = b + l8 * 8;
        uint4 pk;
        unsigned* pw = (unsigned*)&pk;
        #pragma unroll
        for (int u = 0; u < 4; u++) {
            float2 f = __half22float2(sp[u]);
            float ox = fmaxf(fmaf(d2, f.x, acc[2 * u])     + bp[2 * u],     0.f);
            float oy = fmaxf(fmaf(d2, f.y, acc[2 * u + 1]) + bp[2 * u + 1], 0.f);
            __half2 h2 = __floats2half2_rn(ox, oy);
            pw[u] = *(unsigned*)&h2;
        }
        ((uint4*)(g_agg + (size_t)node * 64))[l8] = pk;
    }
}

// ---------------- gather32: final layer, fp32 out, no relu -------------------
__global__ void __launch_bounds__(256)
gather32_kernel(const float* __restrict__ b, float* __restrict__ out) {
    const unsigned FULL = 0xffffffffu;
    int node = (blockIdx.x * blockDim.x + threadIdx.x) >> 5;
    if (node >= N_NODES) return;
    int lane = threadIdx.x & 31;
    int g  = lane >> 2;
    int l4 = lane & 3;

    int start = g_rowstart[node];
    int end   = g_rowstart[node + 1];

    float acc[8];
    #pragma unroll
    for (int t = 0; t < 8; t++) acc[t] = 0.0f;
    const uint4* hb = (const uint4*)g_h;

    #pragma unroll 2
    for (int k = start + g; k < end; k += 8) {
        int2 e = g_csr[k];
        float w = __int_as_float(e.y);
        uint4 v = hb[(unsigned)e.x * 4u + l4];
        const __half2* hp = (const __half2*)&v;
        #pragma unroll
        for (int u = 0; u < 4; u++) {
            float2 f = __half22float2(hp[u]);
            acc[2 * u]     = fmaf(w, f.x, acc[2 * u]);
            acc[2 * u + 1] = fmaf(w, f.y, acc[2 * u + 1]);
        }
    }

    #pragma unroll
    for (int t = 0; t < 8; t++) {
        acc[t] += __shfl_down_sync(FULL, acc[t], 16);
        acc[t] += __shfl_down_sync(FULL, acc[t], 8);
        acc[t] += __shfl_down_sync(FULL, acc[t], 4);
    }

    if (g == 0) {
        float d  = g_dis[node];
        float d2 = d * d;
        uint4 sv = hb[(unsigned)node * 4u + l4];
        const __half2* sp = (const __half2*)&sv;
        float* ap = out + (size_t)node * 32 + l4 * 8;
        const float* bp = b + l4 * 8;
        float o[8];
        #pragma unroll
        for (int u = 0; u < 4; u++) {
            float2 f = __half22float2(sp[u]);
            o[2 * u]     = fmaf(d2, f.x, acc[2 * u])     + bp[2 * u];
            o[2 * u + 1] = fmaf(d2, f.y, acc[2 * u + 1]) + bp[2 * u + 1];
        }
        *(float4*)(ap)     = make_float4(o[0], o[1], o[2], o[3]);
        *(float4*)(ap + 4) = make_float4(o[4], o[5], o[6], o[7]);
    }
}

// ---------------- plain GEMM kernels (layers 2,3) ---------------------------
template <int NOUT>
__global__ void __launch_bounds__(256)
gemm_kernel(const float* __restrict__ W) {
    gemm_body<NOUT, false>(nullptr, W, blockIdx.x, threadIdx.x);
}

// ---------------- launch -----------------------------------------------------
extern "C" void kernel_launch(void* const* d_in, const int* in_sizes, int n_in,
                              void* d_out, int out_size) {
    const float* x    = (const float*)d_in[0];
    const int*   ei32 = (const int*)d_in[1];   // int32 OR int64 (auto-detected)
    const float* W1 = (const float*)d_in[2];
    const float* b1 = (const float*)d_in[3];
    const float* W2 = (const float*)d_in[4];
    const float* b2 = (const float*)d_in[5];
    const float* W3 = (const float*)d_in[6];
    const float* b3 = (const float*)d_in[7];
    float* out = (float*)d_out;

    const int TPB = 256;
    const int gather_blocks = (N_NODES * 32 + TPB - 1) / TPB;  // 1 warp/node

    // 0: gemm1 (tensor cores) + degree hist + lookback-desc reset
    fused_gemm1_hist_kernel<<<GEMM_BLOCKS + HIST_BLOCKS, TPB>>>(x, W1, ei32);
    // 1: single-pass scan (rowstart, dis, fill-init, cnt re-zero)
    scan_kernel<<<SCAN_NB, 1024>>>();
    // 2: CSR fill
    fill_kernel<<<HIST_BLOCKS, TPB>>>(ei32);
    // 3: layer-1 gather (profiled slot)
    gather64_kernel<<<gather_blocks, TPB>>>(b1);
    // layer 2
    gemm_kernel<64><<<GEMM_BLOCKS, TPB>>>(W2);
    gather64_kernel<<<gather_blocks, TPB>>>(b2);
    // layer 3
    gemm_kernel<32><<<GEMM_BLOCKS, TPB>>>(W3);
    gather32_kernel<<<gather_blocks, TPB>>>(b3, out);
}

// round 12
// speedup vs baseline: 2.1888x; 1.0720x over previous
#include <cuda_runtime.h>
#include <cuda_fp16.h>
#include <math.h>

#define N_NODES 100000
#define N_EDGES 1600000
#define SCAN_NB ((N_NODES + 1023) / 1024)       // 98 blocks
#define GEMM_BLOCKS ((N_NODES + 127) / 128)     // 782
#define HIST_BLOCKS ((N_EDGES + 255) / 256)     // 6250

// ---------------- scratch (device globals: no allocation allowed) ----------
__device__ __align__(16) __half g_h[N_NODES * 64];   // h' = dis*(in@W), fp16
__device__ __align__(16) __half g_agg[N_NODES * 64]; // relu(conv) fp16 (L1,L2)
__device__ float g_dis[N_NODES];               // rsqrt(deg+1)
__device__ int   g_cnt[N_NODES];               // in-degree; re-zeroed by scan
__device__ int   g_rowstart[N_NODES + 1];      // CSR row offsets
__device__ int   g_fill[N_NODES];              // atomic fill cursors
__device__ unsigned long long g_desc[SCAN_NB]; // lookback descriptors
__device__ __align__(16) int g_csr[N_EDGES];   // src only (h pre-scaled)

// ---------------- helpers ---------------------------------------------------
__device__ __forceinline__ unsigned load_idx(const int* ei32, long long pos, int is64) {
    unsigned v = is64 ? (unsigned)ei32[2 * pos] : (unsigned)ei32[pos];
    return (v >= N_NODES) ? 0u : v;   // defensive clamp
}

// per-block edge dtype sniff: JAX int64 LE with ids < 2^17 -> odd words all 0
__device__ __forceinline__ int detect_is64_block(const int* ei32, int* s64, int tid) {
    if (tid == 0) {
        int az = 1;
        #pragma unroll
        for (int j = 1; j < 128; j += 2) az &= (ei32[j] == 0);
        *s64 = az;
    }
    __syncthreads();
    return *s64;
}

__device__ __forceinline__ unsigned smem_u32(const void* p) {
    return (unsigned)__cvta_generic_to_shared(p);
}

// ---------------- tensor-core GEMM body: g_h = fp16( dis * (in @ W) ) -------
// 256 threads, 128 nodes/block; mma.sync m16n8k16, fp32 accumulate.
// IN_EXT: fp32 input (x). else: fp16 input (g_agg, relu already applied).
template <int NOUT, bool IN_EXT>
__device__ __forceinline__ void gemm_body(const float* __restrict__ ext_in,
                                          const float* __restrict__ W,
                                          int bidx, int tid) {
    constexpr int AS_STR = 72;            // halves; 144B = 9*16B row stride
    constexpr int WS_STR = (NOUT == 64) ? 72 : 40;
    constexpr int NT = NOUT / 8;
    __shared__ __align__(16) __half As[128 * AS_STR];
    __shared__ __align__(16) __half Ws[64 * WS_STR];

    const int base = bidx * 128;

    #pragma unroll 4
    for (int idx = tid; idx < 64 * NOUT / 2; idx += 256) {
        int row = idx / (NOUT / 2), c2 = idx % (NOUT / 2);
        float2 wv = ((const float2*)W)[idx];
        *(half2*)&Ws[row * WS_STR + c2 * 2] = __floats2half2_rn(wv.x, wv.y);
    }

    {
        int node = tid >> 1;
        int c0 = (tid & 1) * 32;
        int gnode = base + node;
        __half* dst = &As[node * AS_STR + c0];
        if (gnode < N_NODES) {
            if (IN_EXT) {
                const float4* src = (const float4*)(ext_in + (size_t)gnode * 64 + c0);
                #pragma unroll
                for (int i = 0; i < 8; i++) {
                    float4 v = src[i];
                    *(half2*)(dst + i * 4)     = __floats2half2_rn(v.x, v.y);
                    *(half2*)(dst + i * 4 + 2) = __floats2half2_rn(v.z, v.w);
                }
            } else {
                const uint4* src = (const uint4*)(g_agg + (size_t)gnode * 64 + c0);
                #pragma unroll
                for (int i = 0; i < 4; i++)
                    ((uint4*)dst)[i] = src[i];
            }
        } else {
            #pragma unroll
            for (int i = 0; i < 4; i++)
                ((uint4*)dst)[i] = make_uint4(0, 0, 0, 0);
        }
    }
    __syncthreads();

    const int warp = tid >> 5;
    const int lane = tid & 31;
    const int m0 = warp * 16;

    float acc[NT][4];
    #pragma unroll
    for (int n = 0; n < NT; n++)
        #pragma unroll
        for (int i = 0; i < 4; i++) acc[n][i] = 0.0f;

    const unsigned a_base = smem_u32(As);
    const unsigned w_base = smem_u32(Ws);

    #pragma unroll
    for (int ks = 0; ks < 4; ks++) {
        unsigned a0, a1, a2, a3;
        unsigned a_addr = a_base +
            (((m0 + (lane & 15)) * AS_STR + ks * 16 + ((lane >> 4) << 3)) << 1);
        asm volatile("ldmatrix.sync.aligned.m8n8.x4.shared.b16 {%0,%1,%2,%3}, [%4];"
                     : "=r"(a0), "=r"(a1), "=r"(a2), "=r"(a3) : "r"(a_addr));
        #pragma unroll
        for (int nt = 0; nt < NT; nt++) {
            unsigned b0, b1;
            unsigned b_addr = w_base +
                (((ks * 16 + (lane & 15)) * WS_STR + nt * 8) << 1);
            asm volatile("ldmatrix.sync.aligned.m8n8.x2.trans.shared.b16 {%0,%1}, [%2];"
                         : "=r"(b0), "=r"(b1) : "r"(b_addr));
            asm volatile(
                "mma.sync.aligned.m16n8k16.row.col.f32.f16.f16.f32 "
                "{%0,%1,%2,%3},{%4,%5,%6,%7},{%8,%9},{%0,%1,%2,%3};"
                : "+f"(acc[nt][0]), "+f"(acc[nt][1]), "+f"(acc[nt][2]), "+f"(acc[nt][3])
                : "r"(a0), "r"(a1), "r"(a2), "r"(a3), "r"(b0), "r"(b1));
        }
    }

    const int row = lane >> 2;
    const int cp  = (lane & 3) * 2;
    int node0 = base + m0 + row;
    int node1 = node0 + 8;
    float d0 = (node0 < N_NODES) ? g_dis[node0] : 0.f;
    float d1 = (node1 < N_NODES) ? g_dis[node1] : 0.f;
    #pragma unroll
    for (int nt = 0; nt < NT; nt++) {
        if (node0 < N_NODES)
            *(half2*)(g_h + (size_t)node0 * NOUT + nt * 8 + cp) =
                __floats2half2_rn(acc[nt][0] * d0, acc[nt][1] * d0);
        if (node1 < N_NODES)
            *(half2*)(g_h + (size_t)node1 * NOUT + nt * 8 + cp) =
                __floats2half2_rn(acc[nt][2] * d1, acc[nt][3] * d1);
    }
}

// ---------------- launch 0: fused gemm1 + hist + desc reset -----------------
__global__ void __launch_bounds__(256)
fused_gemm1_hist_kernel(const float* __restrict__ x, const float* __restrict__ W1,
                        const int* __restrict__ ei32) {
    __shared__ int s64;
    int tid = threadIdx.x;
    if (blockIdx.x < GEMM_BLOCKS) {
        gemm_body<64, true>(x, W1, blockIdx.x, tid);
    } else {
        int hb = blockIdx.x - GEMM_BLOCKS;
        if (hb == 0 && tid < SCAN_NB) g_desc[tid] = 0ULL;   // reset lookback
        int is64 = detect_is64_block(ei32, &s64, tid);
        int e = hb * 256 + tid;
        if (e < N_EDGES) {
            unsigned d = load_idx(ei32, (long long)N_EDGES + e, is64);
            atomicAdd(&g_cnt[d], 1);
        }
    }
}

// NOTE: gemm1 writes g_h scaled by dis, but dis is computed by scan_kernel
// which runs AFTER gemm1. FIX: gemm1 must not scale. We handle this by having
// gemm1 defer scaling: see scale_h_kernel comment below... (resolved: gemm1
// runs before dis exists only in launch 0; therefore layer-1 scaling is
// folded into the scan-ordering: gemm1 -> hist -> scan -> fill -> scale in
// gather? NO — simplest correct: gemm1 stores UNSCALED h, and gather64 for
// layer 1 multiplies each neighbor row by dis[src]... that reintroduces w.)
// => Resolution used here: launch order moves gemm1 AFTER scan (it only
// needs x/W1), so dis is ready and all gemm epilogues scale uniformly.

// ---------------- hist-only kernel (launch 0 companion) ---------------------
__global__ void __launch_bounds__(256)
hist_kernel(const int* __restrict__ ei32) {
    __shared__ int s64;
    int tid = threadIdx.x;
    if (blockIdx.x == 0 && tid < SCAN_NB) g_desc[tid] = 0ULL;
    int is64 = detect_is64_block(ei32, &s64, tid);
    int e = blockIdx.x * 256 + tid;
    if (e < N_EDGES) {
        unsigned d = load_idx(ei32, (long long)N_EDGES + e, is64);
        atomicAdd(&g_cnt[d], 1);
    }
}

// ---------------- single-pass scan (decoupled lookback) ---------------------
__global__ void __launch_bounds__(1024) scan_kernel() {
    __shared__ int s_warp[32];
    __shared__ int s_prefix;
    const unsigned FULL = 0xffffffffu;
    int tid = threadIdx.x, lane = tid & 31, wid = tid >> 5;
    int bid = blockIdx.x;
    int i = bid * 1024 + tid;
    int v = (i < N_NODES) ? g_cnt[i] : 0;

    int s = v;
    #pragma unroll
    for (int o = 1; o < 32; o <<= 1) {
        int t = __shfl_up_sync(FULL, s, o);
        if (lane >= o) s += t;
    }
    if (lane == 31) s_warp[wid] = s;
    __syncthreads();
    if (wid == 0) {
        int ws = s_warp[lane];
        #pragma unroll
        for (int o = 1; o < 32; o <<= 1) {
            int t = __shfl_up_sync(FULL, ws, o);
            if (lane >= o) ws += t;
        }
        s_warp[lane] = ws;
    }
    __syncthreads();
    int warp_excl = (wid == 0) ? 0 : s_warp[wid - 1];
    int incl  = s + warp_excl;
    int total = s_warp[31];

    if (wid == 0) {
        if (lane == 0) {
            unsigned long long d =
                ((unsigned long long)((bid == 0) ? 2 : 1) << 32) | (unsigned)total;
            atomicExch(&g_desc[bid], d);
        }
        int prefix = 0;
        if (bid > 0) {
            int j = bid - 1;
            while (j >= 0) {
                int idx = j - lane;
                bool valid = idx >= 0;
                unsigned long long d = 0;
                bool done;
                do {
                    if (valid) d = *((volatile unsigned long long*)&g_desc[idx]);
                    done = !valid || (d >> 32) != 0;
                } while (!__all_sync(FULL, done));
                unsigned pm = __ballot_sync(FULL, valid && (d >> 32) == 2);
                int contrib;
                if (pm) {
                    int fp = __ffs(pm) - 1;
                    contrib = (valid && lane <= fp) ? (int)(unsigned)d : 0;
                } else {
                    contrib = valid ? (int)(unsigned)d : 0;
                }
                #pragma unroll
                for (int o = 16; o > 0; o >>= 1)
                    contrib += __shfl_down_sync(FULL, contrib, o);
                if (lane == 0) prefix += contrib;
                if (pm) break;
                j -= 32;
            }
            if (lane == 0)
                atomicExch(&g_desc[bid], (2ULL << 32) | (unsigned)(prefix + total));
        }
        if (lane == 0) s_prefix = prefix;
    }
    __syncthreads();

    int pr = s_prefix;
    if (i < N_NODES) {
        int excl = pr + incl - v;
        g_rowstart[i] = excl;
        g_fill[i]     = excl;
        g_dis[i]      = rsqrtf((float)v + 1.0f);
        g_cnt[i]      = 0;                       // zero-on-entry invariant
    }
    if (bid == 0 && tid == 0) g_rowstart[N_NODES] = N_EDGES;
}

// ---------------- fused gemm1 + fill (both only need scan results) ----------
__global__ void __launch_bounds__(256)
fused_gemm1_fill_kernel(const float* __restrict__ x, const float* __restrict__ W1,
                        const int* __restrict__ ei32) {
    __shared__ int s64;
    int tid = threadIdx.x;
    if (blockIdx.x < GEMM_BLOCKS) {
        gemm_body<64, true>(x, W1, blockIdx.x, tid);
    } else {
        int fb = blockIdx.x - GEMM_BLOCKS;
        int is64 = detect_is64_block(ei32, &s64, tid);
        int e = fb * 256 + tid;
        if (e < N_EDGES) {
            unsigned sn = load_idx(ei32, e, is64);
            unsigned dn = load_idx(ei32, (long long)N_EDGES + e, is64);
            int pos = atomicAdd(&g_fill[dn], 1);
            g_csr[pos] = (int)sn;
        }
    }
}

// ---------------- gather64: agg = fp16(relu(dis*(sum h' + h'self) + b)) ------
// Warp/node; quarter-warp (8 lanes x uint4 = 128B fp16 row) per edge stream.
// Pairwise fp16 pre-add halves cvt+add work; unroll 2 for MLP.
__global__ void __launch_bounds__(256)
gather64_kernel(const float* __restrict__ b) {
    const unsigned FULL = 0xffffffffu;
    int node = (blockIdx.x * blockDim.x + threadIdx.x) >> 5;
    if (node >= N_NODES) return;
    int lane = threadIdx.x & 31;
    int q  = lane >> 3;
    int l8 = lane & 7;

    int start = g_rowstart[node];
    int end   = g_rowstart[node + 1];

    float acc[8];
    #pragma unroll
    for (int t = 0; t < 8; t++) acc[t] = 0.0f;
    const uint4* hb = (const uint4*)g_h;

    int k = start + q;
    #pragma unroll 2
    for (; k + 4 < end; k += 8) {
        int s0 = g_csr[k];
        int s1 = g_csr[k + 4];
        uint4 v0 = hb[(unsigned)s0 * 8u + l8];
        uint4 v1 = hb[(unsigned)s1 * 8u + l8];
        const __half2* p0 = (const __half2*)&v0;
        const __half2* p1 = (const __half2*)&v1;
        #pragma unroll
        for (int u = 0; u < 4; u++) {
            float2 f = __half22float2(__hadd2(p0[u], p1[u]));
            acc[2 * u]     += f.x;
            acc[2 * u + 1] += f.y;
        }
    }
    if (k < end) {
        int s0 = g_csr[k];
        uint4 v0 = hb[(unsigned)s0 * 8u + l8];
        const __half2* p0 = (const __half2*)&v0;
        #pragma unroll
        for (int u = 0; u < 4; u++) {
            float2 f = __half22float2(p0[u]);
            acc[2 * u]     += f.x;
            acc[2 * u + 1] += f.y;
        }
    }

    #pragma unroll
    for (int t = 0; t < 8; t++) {
        acc[t] += __shfl_down_sync(FULL, acc[t], 16);
        acc[t] += __shfl_down_sync(FULL, acc[t], 8);
    }

    if (q == 0) {
        float d  = g_dis[node];
        uint4 sv = hb[(unsigned)node * 8u + l8];
        const __half2* sp = (const __half2*)&sv;
        const float* bp = b + l8 * 8;
        uint4 pk;
        unsigned* pw = (unsigned*)&pk;
        #pragma unroll
        for (int u = 0; u < 4; u++) {
            float2 f = __half22float2(sp[u]);
            float ox = fmaxf(fmaf(d, acc[2 * u]     + f.x, bp[2 * u]),     0.f);
            float oy = fmaxf(fmaf(d, acc[2 * u + 1] + f.y, bp[2 * u + 1]), 0.f);
            __half2 h2 = __floats2half2_rn(ox, oy);
            pw[u] = *(unsigned*)&h2;
        }
        ((uint4*)(g_agg + (size_t)node * 64))[l8] = pk;
    }
}

// ---------------- gather32: final layer, fp32 out, no relu -------------------
__global__ void __launch_bounds__(256)
gather32_kernel(const float* __restrict__ b, float* __restrict__ out) {
    const unsigned FULL = 0xffffffffu;
    int node = (blockIdx.x * blockDim.x + threadIdx.x) >> 5;
    if (node >= N_NODES) return;
    int lane = threadIdx.x & 31;
    int g  = lane >> 2;
    int l4 = lane & 3;

    int start = g_rowstart[node];
    int end   = g_rowstart[node + 1];

    float acc[8];
    #pragma unroll
    for (int t = 0; t < 8; t++) acc[t] = 0.0f;
    const uint4* hb = (const uint4*)g_h;

    int k = start + g;
    #pragma unroll 2
    for (; k + 8 < end; k += 16) {
        int s0 = g_csr[k];
        int s1 = g_csr[k + 8];
        uint4 v0 = hb[(unsigned)s0 * 4u + l4];
        uint4 v1 = hb[(unsigned)s1 * 4u + l4];
        const __half2* p0 = (const __half2*)&v0;
        const __half2* p1 = (const __half2*)&v1;
        #pragma unroll
        for (int u = 0; u < 4; u++) {
            float2 f = __half22float2(__hadd2(p0[u], p1[u]));
            acc[2 * u]     += f.x;
            acc[2 * u + 1] += f.y;
        }
    }
    if (k < end) {
        int s0 = g_csr[k];
        uint4 v0 = hb[(unsigned)s0 * 4u + l4];
        const __half2* p0 = (const __half2*)&v0;
        #pragma unroll
        for (int u = 0; u < 4; u++) {
            float2 f = __half22float2(p0[u]);
            acc[2 * u]     += f.x;
            acc[2 * u + 1] += f.y;
        }
    }

    #pragma unroll
    for (int t = 0; t < 8; t++) {
        acc[t] += __shfl_down_sync(FULL, acc[t], 16);
        acc[t] += __shfl_down_sync(FULL, acc[t], 8);
        acc[t] += __shfl_down_sync(FULL, acc[t], 4);
    }

    if (g == 0) {
        float d  = g_dis[node];
        uint4 sv = hb[(unsigned)node * 4u + l4];
        const __half2* sp = (const __half2*)&sv;
        float* ap = out + (size_t)node * 32 + l4 * 8;
        const float* bp = b + l4 * 8;
        float o[8];
        #pragma unroll
        for (int u = 0; u < 4; u++) {
            float2 f = __half22float2(sp[u]);
            o[2 * u]     = fmaf(d, acc[2 * u]     + f.x, bp[2 * u]);
            o[2 * u + 1] = fmaf(d, acc[2 * u + 1] + f.y, bp[2 * u + 1]);
        }
        *(float4*)(ap)     = make_float4(o[0], o[1], o[2], o[3]);
        *(float4*)(ap + 4) = make_float4(o[4], o[5], o[6], o[7]);
    }
}

// ---------------- plain GEMM kernels (layers 2,3) ---------------------------
template <int NOUT>
__global__ void __launch_bounds__(256)
gemm_kernel(const float* __restrict__ W) {
    gemm_body<NOUT, false>(nullptr, W, blockIdx.x, threadIdx.x);
}

// ---------------- launch -----------------------------------------------------
extern "C" void kernel_launch(void* const* d_in, const int* in_sizes, int n_in,
                              void* d_out, int out_size) {
    const float* x    = (const float*)d_in[0];
    const int*   ei32 = (const int*)d_in[1];   // int32 OR int64 (auto-detected)
    const float* W1 = (const float*)d_in[2];
    const float* b1 = (const float*)d_in[3];
    const float* W2 = (const float*)d_in[4];
    const float* b2 = (const float*)d_in[5];
    const float* W3 = (const float*)d_in[6];
    const float* b3 = (const float*)d_in[7];
    float* out = (float*)d_out;

    const int TPB = 256;
    const int gather_blocks = (N_NODES * 32 + TPB - 1) / TPB;  // 1 warp/node

    // 0: degree hist (+ lookback-desc reset)
    hist_kernel<<<HIST_BLOCKS, TPB>>>(ei32);
    // 1: single-pass scan -> rowstart, dis, fill-init, cnt re-zero
    scan_kernel<<<SCAN_NB, 1024>>>();
    // 2: gemm1 (needs dis for pre-scaling) fused with CSR fill
    fused_gemm1_fill_kernel<<<GEMM_BLOCKS + HIST_BLOCKS, TPB>>>(x, W1, ei32);
    // 3: layer-1 gather (profiled slot)
    gather64_kernel<<<gather_blocks, TPB>>>(b1);
    // layer 2
    gemm_kernel<64><<<GEMM_BLOCKS, TPB>>>(W2);
    gather64_kernel<<<gather_blocks, TPB>>>(b2);
    // layer 3
    gemm_kernel<32><<<GEMM_BLOCKS, TPB>>>(W3);
    gather32_kernel<<<gather_blocks, TPB>>>(b3, out);
}

// round 13
// speedup vs baseline: 2.7116x; 1.2388x over previous
#include <cuda_runtime.h>
#include <cuda_fp16.h>
#include <math.h>

#define N_NODES 100000
#define N_EDGES 1600000
#define SCAN_NB ((N_NODES + 1023) / 1024)       // 98 blocks
#define GEMM_BLOCKS ((N_NODES + 127) / 128)     // 782
#define HIST_BLOCKS ((N_EDGES + 255) / 256)     // 6250

// ---------------- scratch (device globals: no allocation allowed) ----------
__device__ __align__(16) __half g_h[N_NODES * 64];   // h' = dis*(in@W), fp16
__device__ __align__(16) __half g_agg[N_NODES * 64]; // relu(conv) fp16 (L1,L2)
__device__ float g_dis[N_NODES];               // rsqrt(deg+1)
__device__ int   g_cnt[N_NODES];               // in-degree; re-zeroed by scan
__device__ int   g_rowstart[N_NODES + 1];      // CSR row offsets
__device__ int   g_fill[N_NODES];              // atomic fill cursors
__device__ unsigned long long g_desc[SCAN_NB]; // lookback descriptors
__device__ __align__(16) int g_csr[N_EDGES];   // src only (h pre-scaled)

// ---------------- helpers ---------------------------------------------------
__device__ __forceinline__ unsigned load_idx(const int* ei32, long long pos, int is64) {
    unsigned v = is64 ? (unsigned)ei32[2 * pos] : (unsigned)ei32[pos];
    return (v >= N_NODES) ? 0u : v;   // defensive clamp
}

// per-block edge dtype sniff: JAX int64 LE with ids < 2^17 -> odd words all 0
__device__ __forceinline__ int detect_is64_block(const int* ei32, int* s64, int tid) {
    if (tid == 0) {
        int az = 1;
        #pragma unroll
        for (int j = 1; j < 128; j += 2) az &= (ei32[j] == 0);
        *s64 = az;
    }
    __syncthreads();
    return *s64;
}

__device__ __forceinline__ unsigned smem_u32(const void* p) {
    return (unsigned)__cvta_generic_to_shared(p);
}

// ---------------- tensor-core GEMM body: g_h = fp16( dis * (in @ W) ) -------
// 256 threads, 128 nodes/block; mma.sync m16n8k16, fp32 accumulate.
template <int NOUT, bool IN_EXT>
__device__ __forceinline__ void gemm_body(const float* __restrict__ ext_in,
                                          const float* __restrict__ W,
                                          int bidx, int tid) {
    constexpr int AS_STR = 72;            // halves; 144B = 9*16B row stride
    constexpr int WS_STR = (NOUT == 64) ? 72 : 40;
    constexpr int NT = NOUT / 8;
    __shared__ __align__(16) __half As[128 * AS_STR];
    __shared__ __align__(16) __half Ws[64 * WS_STR];

    const int base = bidx * 128;

    #pragma unroll 4
    for (int idx = tid; idx < 64 * NOUT / 2; idx += 256) {
        int row = idx / (NOUT / 2), c2 = idx % (NOUT / 2);
        float2 wv = ((const float2*)W)[idx];
        *(half2*)&Ws[row * WS_STR + c2 * 2] = __floats2half2_rn(wv.x, wv.y);
    }

    {
        int node = tid >> 1;
        int c0 = (tid & 1) * 32;
        int gnode = base + node;
        __half* dst = &As[node * AS_STR + c0];
        if (gnode < N_NODES) {
            if (IN_EXT) {
                const float4* src = (const float4*)(ext_in + (size_t)gnode * 64 + c0);
                #pragma unroll
                for (int i = 0; i < 8; i++) {
                    float4 v = src[i];
                    *(half2*)(dst + i * 4)     = __floats2half2_rn(v.x, v.y);
                    *(half2*)(dst + i * 4 + 2) = __floats2half2_rn(v.z, v.w);
                }
            } else {
                const uint4* src = (const uint4*)(g_agg + (size_t)gnode * 64 + c0);
                #pragma unroll
                for (int i = 0; i < 4; i++)
                    ((uint4*)dst)[i] = src[i];
            }
        } else {
            #pragma unroll
            for (int i = 0; i < 4; i++)
                ((uint4*)dst)[i] = make_uint4(0, 0, 0, 0);
        }
    }
    __syncthreads();

    const int warp = tid >> 5;
    const int lane = tid & 31;
    const int m0 = warp * 16;

    float acc[NT][4];
    #pragma unroll
    for (int n = 0; n < NT; n++)
        #pragma unroll
        for (int i = 0; i < 4; i++) acc[n][i] = 0.0f;

    const unsigned a_base = smem_u32(As);
    const unsigned w_base = smem_u32(Ws);

    #pragma unroll
    for (int ks = 0; ks < 4; ks++) {
        unsigned a0, a1, a2, a3;
        unsigned a_addr = a_base +
            (((m0 + (lane & 15)) * AS_STR + ks * 16 + ((lane >> 4) << 3)) << 1);
        asm volatile("ldmatrix.sync.aligned.m8n8.x4.shared.b16 {%0,%1,%2,%3}, [%4];"
                     : "=r"(a0), "=r"(a1), "=r"(a2), "=r"(a3) : "r"(a_addr));
        #pragma unroll
        for (int nt = 0; nt < NT; nt++) {
            unsigned b0, b1;
            unsigned b_addr = w_base +
                (((ks * 16 + (lane & 15)) * WS_STR + nt * 8) << 1);
            asm volatile("ldmatrix.sync.aligned.m8n8.x2.trans.shared.b16 {%0,%1}, [%2];"
                         : "=r"(b0), "=r"(b1) : "r"(b_addr));
            asm volatile(
                "mma.sync.aligned.m16n8k16.row.col.f32.f16.f16.f32 "
                "{%0,%1,%2,%3},{%4,%5,%6,%7},{%8,%9},{%0,%1,%2,%3};"
                : "+f"(acc[nt][0]), "+f"(acc[nt][1]), "+f"(acc[nt][2]), "+f"(acc[nt][3])
                : "r"(a0), "r"(a1), "r"(a2), "r"(a3), "r"(b0), "r"(b1));
        }
    }

    const int row = lane >> 2;
    const int cp  = (lane & 3) * 2;
    int node0 = base + m0 + row;
    int node1 = node0 + 8;
    float d0 = (node0 < N_NODES) ? g_dis[node0] : 0.f;
    float d1 = (node1 < N_NODES) ? g_dis[node1] : 0.f;
    #pragma unroll
    for (int nt = 0; nt < NT; nt++) {
        if (node0 < N_NODES)
            *(half2*)(g_h + (size_t)node0 * NOUT + nt * 8 + cp) =
                __floats2half2_rn(acc[nt][0] * d0, acc[nt][1] * d0);
        if (node1 < N_NODES)
            *(half2*)(g_h + (size_t)node1 * NOUT + nt * 8 + cp) =
                __floats2half2_rn(acc[nt][2] * d1, acc[nt][3] * d1);
    }
}

// ---------------- launch 0: hist (+ lookback-desc reset) --------------------
__global__ void __launch_bounds__(256)
hist_kernel(const int* __restrict__ ei32) {
    __shared__ int s64;
    int tid = threadIdx.x;
    if (blockIdx.x == 0 && tid < SCAN_NB) g_desc[tid] = 0ULL;
    int is64 = detect_is64_block(ei32, &s64, tid);
    int e = blockIdx.x * 256 + tid;
    if (e < N_EDGES) {
        unsigned d = load_idx(ei32, (long long)N_EDGES + e, is64);
        atomicAdd(&g_cnt[d], 1);
    }
}

// ---------------- launch 1: single-pass scan (decoupled lookback) -----------
__global__ void __launch_bounds__(1024) scan_kernel() {
    __shared__ int s_warp[32];
    __shared__ int s_prefix;
    const unsigned FULL = 0xffffffffu;
    int tid = threadIdx.x, lane = tid & 31, wid = tid >> 5;
    int bid = blockIdx.x;
    int i = bid * 1024 + tid;
    int v = (i < N_NODES) ? g_cnt[i] : 0;

    int s = v;
    #pragma unroll
    for (int o = 1; o < 32; o <<= 1) {
        int t = __shfl_up_sync(FULL, s, o);
        if (lane >= o) s += t;
    }
    if (lane == 31) s_warp[wid] = s;
    __syncthreads();
    if (wid == 0) {
        int ws = s_warp[lane];
        #pragma unroll
        for (int o = 1; o < 32; o <<= 1) {
            int t = __shfl_up_sync(FULL, ws, o);
            if (lane >= o) ws += t;
        }
        s_warp[lane] = ws;
    }
    __syncthreads();
    int warp_excl = (wid == 0) ? 0 : s_warp[wid - 1];
    int incl  = s + warp_excl;
    int total = s_warp[31];

    if (wid == 0) {
        if (lane == 0) {
            unsigned long long d =
                ((unsigned long long)((bid == 0) ? 2 : 1) << 32) | (unsigned)total;
            atomicExch(&g_desc[bid], d);
        }
        int prefix = 0;
        if (bid > 0) {
            int j = bid - 1;
            while (j >= 0) {
                int idx = j - lane;
                bool valid = idx >= 0;
                unsigned long long d = 0;
                bool done;
                do {
                    if (valid) d = *((volatile unsigned long long*)&g_desc[idx]);
                    done = !valid || (d >> 32) != 0;
                } while (!__all_sync(FULL, done));
                unsigned pm = __ballot_sync(FULL, valid && (d >> 32) == 2);
                int contrib;
                if (pm) {
                    int fp = __ffs(pm) - 1;
                    contrib = (valid && lane <= fp) ? (int)(unsigned)d : 0;
                } else {
                    contrib = valid ? (int)(unsigned)d : 0;
                }
                #pragma unroll
                for (int o = 16; o > 0; o >>= 1)
                    contrib += __shfl_down_sync(FULL, contrib, o);
                if (lane == 0) prefix += contrib;
                if (pm) break;
                j -= 32;
            }
            if (lane == 0)
                atomicExch(&g_desc[bid], (2ULL << 32) | (unsigned)(prefix + total));
        }
        if (lane == 0) s_prefix = prefix;
    }
    __syncthreads();

    int pr = s_prefix;
    if (i < N_NODES) {
        int excl = pr + incl - v;
        g_rowstart[i] = excl;
        g_fill[i]     = excl;
        g_dis[i]      = rsqrtf((float)v + 1.0f);
        g_cnt[i]      = 0;                       // zero-on-entry invariant
    }
    if (bid == 0 && tid == 0) g_rowstart[N_NODES] = N_EDGES;
}

// ---------------- launch 2: fused gemm1 + CSR fill --------------------------
__global__ void __launch_bounds__(256)
fused_gemm1_fill_kernel(const float* __restrict__ x, const float* __restrict__ W1,
                        const int* __restrict__ ei32) {
    __shared__ int s64;
    int tid = threadIdx.x;
    if (blockIdx.x < GEMM_BLOCKS) {
        gemm_body<64, true>(x, W1, blockIdx.x, tid);
    } else {
        int fb = blockIdx.x - GEMM_BLOCKS;
        int is64 = detect_is64_block(ei32, &s64, tid);
        int e = fb * 256 + tid;
        if (e < N_EDGES) {
            unsigned sn = load_idx(ei32, e, is64);
            unsigned dn = load_idx(ei32, (long long)N_EDGES + e, is64);
            int pos = atomicAdd(&g_fill[dn], 1);
            g_csr[pos] = (int)sn;
        }
    }
}

// ---------------- gather64: agg = fp16(relu(dis*(sum h' + h'self) + b)) ------
// 8-lane group PER NODE (4 nodes/warp): no cross-group reduction, full-width
// epilogue. Pairwise fp16 pre-add; unroll 2 -> 16 row-loads in flight/warp.
__global__ void __launch_bounds__(256)
gather64_kernel(const float* __restrict__ b) {
    int node = (blockIdx.x * blockDim.x + threadIdx.x) >> 3;
    if (node >= N_NODES) return;
    int l8 = threadIdx.x & 7;

    // bias slice (uniform across nodes) preloaded
    float4 bv0 = ((const float4*)b)[l8 * 2];
    float4 bv1 = ((const float4*)b)[l8 * 2 + 1];

    int start = g_rowstart[node];
    int end   = g_rowstart[node + 1];

    float acc[8];
    #pragma unroll
    for (int t = 0; t < 8; t++) acc[t] = 0.0f;
    const uint4* hb = (const uint4*)g_h;

    int k = start;
    #pragma unroll 2
    for (; k + 1 < end; k += 2) {
        int s0 = g_csr[k];
        int s1 = g_csr[k + 1];
        uint4 v0 = hb[(unsigned)s0 * 8u + l8];
        uint4 v1 = hb[(unsigned)s1 * 8u + l8];
        const __half2* p0 = (const __half2*)&v0;
        const __half2* p1 = (const __half2*)&v1;
        #pragma unroll
        for (int u = 0; u < 4; u++) {
            float2 f = __half22float2(__hadd2(p0[u], p1[u]));
            acc[2 * u]     += f.x;
            acc[2 * u + 1] += f.y;
        }
    }
    if (k < end) {
        int s0 = g_csr[k];
        uint4 v0 = hb[(unsigned)s0 * 8u + l8];
        const __half2* p0 = (const __half2*)&v0;
        #pragma unroll
        for (int u = 0; u < 4; u++) {
            float2 f = __half22float2(p0[u]);
            acc[2 * u]     += f.x;
            acc[2 * u + 1] += f.y;
        }
    }

    // self-loop + scale + bias + relu, pack fp16
    float d = g_dis[node];
    uint4 sv = hb[(unsigned)node * 8u + l8];
    const __half2* sp = (const __half2*)&sv;
    const float* bp0 = (const float*)&bv0;
    const float* bp1 = (const float*)&bv1;
    uint4 pk;
    unsigned* pw = (unsigned*)&pk;
    #pragma unroll
    for (int u = 0; u < 4; u++) {
        float2 f = __half22float2(sp[u]);
        float bx = (u < 2) ? bp0[2 * u]     : bp1[2 * u - 4];
        float by = (u < 2) ? bp0[2 * u + 1] : bp1[2 * u - 3];
        float ox = fmaxf(fmaf(d, acc[2 * u]     + f.x, bx), 0.f);
        float oy = fmaxf(fmaf(d, acc[2 * u + 1] + f.y, by), 0.f);
        __half2 h2 = __floats2half2_rn(ox, oy);
        pw[u] = *(unsigned*)&h2;
    }
    ((uint4*)(g_agg + (size_t)node * 64))[l8] = pk;
}

// ---------------- gather32: 4-lane group per node, fp32 out, no relu ---------
__global__ void __launch_bounds__(256)
gather32_kernel(const float* __restrict__ b, float* __restrict__ out) {
    int node = (blockIdx.x * blockDim.x + threadIdx.x) >> 2;
    if (node >= N_NODES) return;
    int l4 = threadIdx.x & 3;

    float4 bv0 = ((const float4*)b)[l4 * 2];
    float4 bv1 = ((const float4*)b)[l4 * 2 + 1];

    int start = g_rowstart[node];
    int end   = g_rowstart[node + 1];

    float acc[8];
    #pragma unroll
    for (int t = 0; t < 8; t++) acc[t] = 0.0f;
    const uint4* hb = (const uint4*)g_h;

    int k = start;
    #pragma unroll 2
    for (; k + 1 < end; k += 2) {
        int s0 = g_csr[k];
        int s1 = g_csr[k + 1];
        uint4 v0 = hb[(unsigned)s0 * 4u + l4];
        uint4 v1 = hb[(unsigned)s1 * 4u + l4];
        const __half2* p0 = (const __half2*)&v0;
        const __half2* p1 = (const __half2*)&v1;
        #pragma unroll
        for (int u = 0; u < 4; u++) {
            float2 f = __half22float2(__hadd2(p0[u], p1[u]));
            acc[2 * u]     += f.x;
            acc[2 * u + 1] += f.y;
        }
    }
    if (k < end) {
        int s0 = g_csr[k];
        uint4 v0 = hb[(unsigned)s0 * 4u + l4];
        const __half2* p0 = (const __half2*)&v0;
        #pragma unroll
        for (int u = 0; u < 4; u++) {
            float2 f = __half22float2(p0[u]);
            acc[2 * u]     += f.x;
            acc[2 * u + 1] += f.y;
        }
    }

    float d = g_dis[node];
    uint4 sv = hb[(unsigned)node * 4u + l4];
    const __half2* sp = (const __half2*)&sv;
    const float* bp0 = (const float*)&bv0;
    const float* bp1 = (const float*)&bv1;
    float o[8];
    #pragma unroll
    for (int u = 0; u < 4; u++) {
        float2 f = __half22float2(sp[u]);
        float bx = (u < 2) ? bp0[2 * u]     : bp1[2 * u - 4];
        float by = (u < 2) ? bp0[2 * u + 1] : bp1[2 * u - 3];
        o[2 * u]     = fmaf(d, acc[2 * u]     + f.x, bx);
        o[2 * u + 1] = fmaf(d, acc[2 * u + 1] + f.y, by);
    }
    float* ap = out + (size_t)node * 32 + l4 * 8;
    *(float4*)(ap)     = make_float4(o[0], o[1], o[2], o[3]);
    *(float4*)(ap + 4) = make_float4(o[4], o[5], o[6], o[7]);
}

// ---------------- plain GEMM kernels (layers 2,3) ---------------------------
template <int NOUT>
__global__ void __launch_bounds__(256)
gemm_kernel(const float* __restrict__ W) {
    gemm_body<NOUT, false>(nullptr, W, blockIdx.x, threadIdx.x);
}

// ---------------- launch -----------------------------------------------------
extern "C" void kernel_launch(void* const* d_in, const int* in_sizes, int n_in,
                              void* d_out, int out_size) {
    const float* x    = (const float*)d_in[0];
    const int*   ei32 = (const int*)d_in[1];   // int32 OR int64 (auto-detected)
    const float* W1 = (const float*)d_in[2];
    const float* b1 = (const float*)d_in[3];
    const float* W2 = (const float*)d_in[4];
    const float* b2 = (const float*)d_in[5];
    const float* W3 = (const float*)d_in[6];
    const float* b3 = (const float*)d_in[7];
    float* out = (float*)d_out;

    const int TPB = 256;
    const int g64_blocks = (N_NODES * 8 + TPB - 1) / TPB;   // 8 lanes/node
    const int g32_blocks = (N_NODES * 4 + TPB - 1) / TPB;   // 4 lanes/node

    // 0: degree hist (+ lookback-desc reset)
    hist_kernel<<<HIST_BLOCKS, TPB>>>(ei32);
    // 1: single-pass scan -> rowstart, dis, fill-init, cnt re-zero
    scan_kernel<<<SCAN_NB, 1024>>>();
    // 2: gemm1 (needs dis for pre-scaling) fused with CSR fill
    fused_gemm1_fill_kernel<<<GEMM_BLOCKS + HIST_BLOCKS, TPB>>>(x, W1, ei32);
    // 3: layer-1 gather (profiled slot)
    gather64_kernel<<<g64_blocks, TPB>>>(b1);
    // layer 2
    gemm_kernel<64><<<GEMM_BLOCKS, TPB>>>(W2);
    gather64_kernel<<<g64_blocks, TPB>>>(b2);
    // layer 3
    gemm_kernel<32><<<GEMM_BLOCKS, TPB>>>(W3);
    gather32_kernel<<<g32_blocks, TPB>>>(b3, out);
}